// round 11
// baseline (speedup 1.0000x reference)
#include <cuda_runtime.h>
#include <cuda_bf16.h>

// ============================================================================
// TransitionDown: FPS (M=8192 of N=32768) + kNN(16) + Linear+BN+ReLU + max-pool
// Output layout (float32): [out 8192x256][sub_pos 8192x3][sub_batch 8192]
// All arithmetic exact f32. FPS uses mbarrier cross-CTA signaling with
// coordinates carried through the reduction (no pos[] LDG on critical path).
// ============================================================================

#define NPTS   32768
#define CIN    128
#define COUT   256
#define KNN_K  16
#define MCL    8192

#define FPS_CTAS    8
#define FPS_THREADS 512
#define PPT         8   // points per thread: 8*512*8 = 32768

// ---------------- device scratch (static; no allocation allowed) ------------
__device__ float4 g_pos4[NPTS];            // {x,y,z, |p|^2} exact f32
__device__ int    g_idx[MCL];              // FPS-selected indices
__device__ int    g_nbr[MCL * KNN_K];      // kNN indices
__device__ float  g_h[NPTS * COUT];        // linear output (pre-BN)
__device__ float  g_psum[256 * COUT];
__device__ float  g_psumsq[256 * COUT];
__device__ float  g_scale[COUT];
__device__ float  g_shift[COUT];

// ---------------- small helpers ---------------------------------------------
__device__ __forceinline__ float finf() { return __int_as_float(0x7f800000); }
__device__ __forceinline__ float fninf() { return __int_as_float(0xff800000); }

__device__ __forceinline__ unsigned long long pk2(float a, float b) {
    unsigned long long r;
    asm("mov.b64 %0, {%1, %2};" : "=l"(r) : "f"(a), "f"(b));
    return r;
}
__device__ __forceinline__ void upk2(unsigned long long v, float& a, float& b) {
    asm("mov.b64 {%0, %1}, %2;" : "=f"(a), "=f"(b) : "l"(v));
}
__device__ __forceinline__ unsigned long long add2(unsigned long long a, unsigned long long b) {
    unsigned long long r;
    asm("add.rn.f32x2 %0, %1, %2;" : "=l"(r) : "l"(a), "l"(b));
    return r;
}
__device__ __forceinline__ unsigned long long mul2(unsigned long long a, unsigned long long b) {
    unsigned long long r;
    asm("mul.rn.f32x2 %0, %1, %2;" : "=l"(r) : "l"(a), "l"(b));
    return r;
}
// store u64 into the same smem offset of a peer CTA in the cluster
__device__ __forceinline__ void st_cluster_u64(unsigned laddr, unsigned rank,
                                               unsigned long long v) {
    asm volatile(
        "{\n\t"
        ".reg .b32 ra;\n\t"
        "mapa.shared::cluster.u32 ra, %0, %1;\n\t"
        "st.shared::cluster.u64 [ra], %2;\n\t"
        "}"
        :: "r"(laddr), "r"(rank), "l"(v) : "memory");
}
// arrive (release, cluster scope) on the mbarrier at the same offset in CTA `rank`
__device__ __forceinline__ void mbar_arrive_remote(unsigned local_mbar, unsigned rank) {
    asm volatile(
        "{\n\t"
        ".reg .b32 ra;\n\t"
        "mapa.shared::cluster.u32 ra, %0, %1;\n\t"
        "mbarrier.arrive.release.cluster.shared::cluster.b64 _, [ra];\n\t"
        "}"
        :: "r"(local_mbar), "r"(rank) : "memory");
}
__device__ __forceinline__ void mbar_wait_cluster(unsigned addr, unsigned parity) {
    unsigned done;
    asm volatile(
        "{\n\t.reg .pred p;\n\t"
        "mbarrier.try_wait.parity.acquire.cluster.shared::cta.b64 p, [%1], %2;\n\t"
        "selp.b32 %0, 1, 0, p;\n\t}"
        : "=r"(done) : "r"(addr), "r"(parity) : "memory");
    while (!done) {
        asm volatile(
            "{\n\t.reg .pred p;\n\t"
            "mbarrier.try_wait.parity.acquire.cluster.shared::cta.b64 p, [%1], %2;\n\t"
            "selp.b32 %0, 1, 0, p;\n\t}"
            : "=r"(done) : "r"(addr), "r"(parity) : "memory");
    }
}
__device__ __forceinline__ unsigned cluster_rank() {
    unsigned r;
    asm("mov.u32 %0, %%cluster_ctarank;" : "=r"(r));
    return r;
}

// ============================================================================
// 0) prep: pos4 table {x,y,z, |p|^2} exact f32
// ============================================================================
__global__ void prep_kernel(const float* __restrict__ pos) {
    int i = blockIdx.x * blockDim.x + threadIdx.x;
    if (i >= NPTS) return;
    float x = pos[3 * i + 0];
    float y = pos[3 * i + 1];
    float z = pos[3 * i + 2];
    float n = __fadd_rn(__fadd_rn(__fmul_rn(x, x), __fmul_rn(y, y)), __fmul_rn(z, z));
    g_pos4[i] = make_float4(x, y, z, n);
}

// ============================================================================
// 1) FPS: 8-CTA cluster, points register-resident.
//    Per round: compute -> warp bfly argmax (coords extracted by owner lane
//    into smem slot) -> syncthreads -> warp0 reduces 16 slots, lanes 0-7 push
//    {key,xy,z} to all CTAs via DSMEM + mbarrier arrive -> all threads wait
//    local mbarrier -> all threads reduce 8 cross slots -> center in regs.
//    Exact f32, reference op order ((dx2+dy2)+dz2); argmax key packs
//    (dist_bits<<32)|(~idx) -> first-index tie like jnp.argmax.
//
//    Race-freedom: cross slots are parity double-buffered. A CTA can push
//    round it+1 only after completing wait(it), which requires every CTA to
//    have pushed round it; a CTA pushes round it only after its own reads of
//    round it-1 finished. Hence writers are at most 1 round ahead of the
//    slowest reader -> 2-deep parity buffer suffices. s_wslots likewise.
// ============================================================================
__global__ void __cluster_dims__(FPS_CTAS, 1, 1) __launch_bounds__(FPS_THREADS, 1)
fps_kernel(const float* __restrict__ pos) {
    // slot layout: [key, xy, z, pad] per entry (32B)
    __shared__ unsigned long long s_wslots[2][16][4];
    __shared__ unsigned long long s_cross[2][FPS_CTAS][4];
    __shared__ __align__(8) unsigned long long s_mbar;

    const int tid = threadIdx.x;
    const int lane = tid & 31;
    const int wid = tid >> 5;
    const unsigned rank = cluster_rank();
    const int p0 = (int)(rank * FPS_THREADS + tid) * PPT;

    const unsigned mbar_addr = (unsigned)__cvta_generic_to_shared(&s_mbar);
    const unsigned cross_base = (unsigned)__cvta_generic_to_shared(&s_cross[0][0][0]);

    if (tid == 0) {
        asm volatile("mbarrier.init.shared.b64 [%0], %1;"
                     :: "r"(mbar_addr), "r"(FPS_CTAS) : "memory");
        if (rank == 0) g_idx[0] = 0;
    }

    unsigned long long X[PPT / 2], Y[PPT / 2], Z[PPT / 2];
    float md[PPT];
#pragma unroll
    for (int pr = 0; pr < PPT / 2; ++pr) {
        int a = p0 + 2 * pr, b = a + 1;
        X[pr] = pk2(pos[3 * a + 0], pos[3 * b + 0]);
        Y[pr] = pk2(pos[3 * a + 1], pos[3 * b + 1]);
        Z[pr] = pk2(pos[3 * a + 2], pos[3 * b + 2]);
    }
#pragma unroll
    for (int j = 0; j < PPT; ++j) md[j] = finf();

    float cx = pos[0], cy = pos[1], cz = pos[2];

    // all mbarriers initialized before any cross-CTA traffic
    asm volatile("barrier.cluster.arrive.aligned;" ::: "memory");
    asm volatile("barrier.cluster.wait.aligned;" ::: "memory");

    unsigned ph = 0;

    for (int it = 1; it < MCL; ++it) {
        const int par = it & 1;
        unsigned long long ncx = pk2(-cx, -cx);
        unsigned long long ncy = pk2(-cy, -cy);
        unsigned long long ncz = pk2(-cz, -cz);

        float bv = fninf();
        int bi = p0;
#pragma unroll
        for (int pr = 0; pr < PPT / 2; ++pr) {
            unsigned long long ax = add2(X[pr], ncx);   // p + (-c) == p - c (IEEE-exact)
            unsigned long long ay = add2(Y[pr], ncy);
            unsigned long long az = add2(Z[pr], ncz);
            unsigned long long sx = mul2(ax, ax);
            unsigned long long sy = mul2(ay, ay);
            unsigned long long sz = mul2(az, az);
            unsigned long long s = add2(add2(sx, sy), sz);  // (dx2+dy2)+dz2
            float d0, d1;
            upk2(s, d0, d1);
            float m0 = fminf(md[2 * pr + 0], d0);
            md[2 * pr + 0] = m0;
            if (m0 > bv) { bv = m0; bi = p0 + 2 * pr + 0; }   // strict >: first idx wins
            float m1 = fminf(md[2 * pr + 1], d1);
            md[2 * pr + 1] = m1;
            if (m1 > bv) { bv = m1; bi = p0 + 2 * pr + 1; }
        }

        unsigned long long key =
            ((unsigned long long)__float_as_uint(bv) << 32) |
            (unsigned)(0xFFFFFFFFu - (unsigned)bi);
        // butterfly: every lane ends with the warp max
#pragma unroll
        for (int o = 16; o > 0; o >>= 1) {
            unsigned long long k2 = __shfl_xor_sync(0xFFFFFFFFu, key, o);
            if (k2 > key) key = k2;
        }
        // owner lane of the warp winner extracts coords and writes the slot
        unsigned wbi = 0xFFFFFFFFu - (unsigned)key;
        int owner = (int)((wbi >> 3) & 31u);
        if (lane == owner) {
            int j = (int)(wbi & 7u);
            float px = 0.f, py = 0.f, pz = 0.f;
#pragma unroll
            for (int pr = 0; pr < PPT / 2; ++pr) {
                float a, b; upk2(X[pr], a, b);
                float c, d; upk2(Y[pr], c, d);
                float e, f; upk2(Z[pr], e, f);
                if ((j >> 1) == pr) {
                    px = (j & 1) ? b : a;
                    py = (j & 1) ? d : c;
                    pz = (j & 1) ? f : e;
                }
            }
            s_wslots[par][wid][0] = key;
            s_wslots[par][wid][1] = pk2(px, py);
            s_wslots[par][wid][2] = pk2(pz, 0.0f);
        }
        __syncthreads();

        if (wid == 0) {
            // reduce the 16 warp slots (lanes 16-31 mirror 0-15; max unaffected)
            unsigned long long k = s_wslots[par][lane & 15][0];
#pragma unroll
            for (int o = 16; o > 0; o >>= 1) {
                unsigned long long k2 = __shfl_xor_sync(0xFFFFFFFFu, k, o);
                if (k2 > k) k = k2;
            }
            unsigned wbi2 = 0xFFFFFFFFu - (unsigned)k;
            int w = (int)(((wbi2 >> 3) & 511u) >> 5);  // winning warp in this CTA
            unsigned long long xy = s_wslots[par][w][1];
            unsigned long long zz = s_wslots[par][w][2];
            if (lane < FPS_CTAS) {
                unsigned base = cross_base + (unsigned)((par * FPS_CTAS + (int)rank) * 4) * 8u;
                st_cluster_u64(base + 0, (unsigned)lane, k);
                st_cluster_u64(base + 8, (unsigned)lane, xy);
                st_cluster_u64(base + 16, (unsigned)lane, zz);
                mbar_arrive_remote(mbar_addr, (unsigned)lane);
            }
        }

        mbar_wait_cluster(mbar_addr, ph);
        ph ^= 1;

        // every thread redundantly reduces the 8 cross keys -> new center
        unsigned long long g = s_cross[par][0][0];
        int rw = 0;
#pragma unroll
        for (int r = 1; r < FPS_CTAS; ++r) {
            unsigned long long k2 = s_cross[par][r][0];
            if (k2 > g) { g = k2; rw = r; }
        }
        float dummy;
        upk2(s_cross[par][rw][1], cx, cy);
        upk2(s_cross[par][rw][2], cz, dummy);
        if (rank == 0 && tid == 0)
            g_idx[it] = (int)(0xFFFFFFFFu - (unsigned)g);
    }
}

// ============================================================================
// 2) meta: sub_pos / sub_batch outputs
// ============================================================================
__global__ void meta_kernel(const float* __restrict__ pos,
                            const int* __restrict__ batch,
                            float* outPos, int* outBatch,
                            int writePos, int writeBatch) {
    int m = blockIdx.x * blockDim.x + threadIdx.x;
    if (m >= MCL) return;
    int idx = g_idx[m];
    if (writePos) {
        outPos[3 * m + 0] = pos[3 * idx + 0];
        outPos[3 * m + 1] = pos[3 * idx + 1];
        outPos[3 * m + 2] = pos[3 * idx + 2];
    }
    if (writeBatch) outBatch[m] = batch[idx];
}

// ============================================================================
// 3) kNN: 8 lanes/query, smem-tiled pos4, register top-16, shuffle pop-merge.
//    d = (|q|^2 - 2*dot) + |p|^2, exact f32 (identical to R10 numerics).
//    Merge key: total-order float encoding; ties break on global index.
// ============================================================================
#define KNN_TILE 2048
__global__ void __launch_bounds__(256) knn_kernel() {
    __shared__ float4 s_p[KNN_TILE];
    const int tid = threadIdx.x;
    const int q = blockIdx.x * 32 + (tid >> 3);
    const int s = tid & 7;

    const int ci = g_idx[q];
    const float4 qp = g_pos4[ci];

    float dist[KNN_K];
    int idn[KNN_K];
#pragma unroll
    for (int u = 0; u < KNN_K; ++u) { dist[u] = finf(); idn[u] = 0; }

    for (int t0 = 0; t0 < NPTS; t0 += KNN_TILE) {
        __syncthreads();
        for (int i = tid; i < KNN_TILE; i += 256) s_p[i] = g_pos4[t0 + i];
        __syncthreads();
        for (int t = s; t < KNN_TILE; t += 8) {
            float4 p = s_p[t];
            float dot = __fadd_rn(__fadd_rn(__fmul_rn(qp.x, p.x),
                                            __fmul_rn(qp.y, p.y)),
                                  __fmul_rn(qp.z, p.z));
            float d = __fadd_rn(__fsub_rn(qp.w, __fmul_rn(2.0f, dot)), p.w);
            if (d < dist[KNN_K - 1]) {
                dist[KNN_K - 1] = d;
                idn[KNN_K - 1] = t0 + t;
#pragma unroll
                for (int u = KNN_K - 1; u > 0; --u) {
                    if (dist[u] < dist[u - 1]) {
                        float td = dist[u]; dist[u] = dist[u - 1]; dist[u - 1] = td;
                        int ti = idn[u]; idn[u] = idn[u - 1]; idn[u - 1] = ti;
                    }
                }
            }
        }
    }

#pragma unroll 1
    for (int r = 0; r < KNN_K; ++r) {
        unsigned db = __float_as_uint(dist[0]);
        db = (db & 0x80000000u) ? ~db : (db | 0x80000000u);  // total order
        unsigned long long key =
            ((unsigned long long)db << 32) |
            (unsigned)((idn[0] << 3) | s);
#pragma unroll
        for (int o = 1; o < 8; o <<= 1) {
            unsigned long long k2 = __shfl_xor_sync(0xFFFFFFFFu, key, o, 8);
            if (k2 < key) key = k2;
        }
        int wl = (int)(key & 7u);
        int hid = (int)((key >> 3) & 0x7FFFu);
        if (s == 0) g_nbr[q * KNN_K + r] = hid;
        if (s == wl) {  // pop my head
#pragma unroll
            for (int u = 0; u < KNN_K - 1; ++u) {
                dist[u] = dist[u + 1];
                idn[u] = idn[u + 1];
            }
            dist[KNN_K - 1] = finf();
        }
    }
}

// ============================================================================
// 4) GEMM: h = x @ W + b, exact f32 FFMA, 64x64 tiles
// ============================================================================
__global__ void __launch_bounds__(256) gemm_kernel(const float* __restrict__ Xm,
                                                   const float* __restrict__ Wm,
                                                   const float* __restrict__ Bv) {
    __shared__ __align__(16) float As[32][72];  // A transposed [k][row], padded
    __shared__ __align__(16) float Bs[32][64];  // [k][col]

    const int tid = threadIdx.x;
    const int tx = tid & 15, ty = tid >> 4;
    const int r0 = blockIdx.x * 64;
    const int c0 = blockIdx.y * 64;

    float acc[4][4];
#pragma unroll
    for (int i = 0; i < 4; ++i)
#pragma unroll
        for (int j = 0; j < 4; ++j) acc[i][j] = 0.0f;

    for (int kc = 0; kc < CIN; kc += 32) {
        __syncthreads();
#pragma unroll
        for (int l = 0; l < 2; ++l) {  // A: 64 rows x 32 k = 512 float4
            int fi = tid * 2 + l;
            int row = fi >> 3;
            int kf = fi & 7;
            float4 a = *(const float4*)&Xm[(r0 + row) * CIN + kc + kf * 4];
            As[kf * 4 + 0][row] = a.x;
            As[kf * 4 + 1][row] = a.y;
            As[kf * 4 + 2][row] = a.z;
            As[kf * 4 + 3][row] = a.w;
        }
#pragma unroll
        for (int l = 0; l < 2; ++l) {  // B: 32 k x 64 cols = 512 float4
            int fi = tid * 2 + l;
            int kk = fi >> 4;
            int cf = fi & 15;
            *(float4*)&Bs[kk][cf * 4] =
                *(const float4*)&Wm[(kc + kk) * COUT + c0 + cf * 4];
        }
        __syncthreads();
#pragma unroll
        for (int kk = 0; kk < 32; ++kk) {
            float4 a = *(float4*)&As[kk][ty * 4];
            float4 b = *(float4*)&Bs[kk][tx * 4];
            float av[4] = {a.x, a.y, a.z, a.w};
            float bv[4] = {b.x, b.y, b.z, b.w};
#pragma unroll
            for (int i = 0; i < 4; ++i)
#pragma unroll
                for (int j = 0; j < 4; ++j) acc[i][j] = fmaf(av[i], bv[j], acc[i][j]);
        }
    }

    float4 bias = *(const float4*)&Bv[c0 + tx * 4];
#pragma unroll
    for (int i = 0; i < 4; ++i) {
        float4 o;
        o.x = acc[i][0] + bias.x;
        o.y = acc[i][1] + bias.y;
        o.z = acc[i][2] + bias.z;
        o.w = acc[i][3] + bias.w;
        *(float4*)&g_h[(r0 + ty * 4 + i) * COUT + c0 + tx * 4] = o;
    }
}

// ============================================================================
// 5) BatchNorm stats: deterministic two-stage tree (no float atomics)
// ============================================================================
__global__ void bn_part_kernel() {
    const int c = threadIdx.x;
    const int b = blockIdx.x;
    const float* hp = g_h + (size_t)b * 128 * COUT;
    float s = 0.0f, ss = 0.0f;
#pragma unroll 4
    for (int r = 0; r < 128; ++r) {
        float v = hp[r * COUT + c];
        s += v;
        ss = fmaf(v, v, ss);
    }
    g_psum[b * COUT + c] = s;
    g_psumsq[b * COUT + c] = ss;
}

__global__ void bn_final_kernel(const float* __restrict__ gamma,
                                const float* __restrict__ beta) {
    const int c = threadIdx.x;
    float s = 0.0f, ss = 0.0f;
    for (int b = 0; b < 256; ++b) {
        s += g_psum[b * COUT + c];
        ss += g_psumsq[b * COUT + c];
    }
    const float invN = 1.0f / (float)NPTS;
    float mu = s * invN;
    float var = ss * invN - mu * mu;
    var = fmaxf(var, 0.0f);
    float sc = gamma[c] * (1.0f / sqrtf(var + 1e-5f));
    g_scale[c] = sc;
    g_shift[c] = beta[c] - mu * sc;
}

// ============================================================================
// 6) gather-max with fused BN+ReLU per gathered element
// ============================================================================
__global__ void __launch_bounds__(256) gather_kernel(float* __restrict__ out) {
    const int m = blockIdx.x;
    const int c = threadIdx.x;
    const float sc = g_scale[c];
    const float sh = g_shift[c];
    float acc = fninf();
#pragma unroll
    for (int k = 0; k < KNN_K; ++k) {
        int id = g_nbr[m * KNN_K + k];
        float v = g_h[(size_t)id * COUT + c];
        float bn = fmaxf(fmaf(v, sc, sh), 0.0f);  // ReLU(BN(v))
        acc = fmaxf(acc, bn);
    }
    out[m * COUT + c] = acc;
}

// ============================================================================
// launch
// ============================================================================
extern "C" void kernel_launch(void* const* d_in, const int* in_sizes, int n_in,
                              void* d_out, int out_size) {
    const float* x     = (const float*)d_in[0];  // [32768,128]
    const float* pos   = (const float*)d_in[1];  // [32768,3]
    const int*   batch = (const int*)d_in[2];    // [32768]
    const float* W     = (const float*)d_in[3];  // [128,256]
    const float* b     = (const float*)d_in[4];  // [256]
    const float* gamma = (const float*)d_in[5];  // [256]
    const float* beta  = (const float*)d_in[6];  // [256]
    float* out = (float*)d_out;

    const int baseOut = MCL * COUT;              // 2097152
    const int writePos = (out_size >= baseOut + MCL * 3) ? 1 : 0;
    const int writeBatch = (out_size >= baseOut + MCL * 3 + MCL) ? 1 : 0;

    prep_kernel<<<NPTS / 256, 256>>>(pos);
    fps_kernel<<<FPS_CTAS, FPS_THREADS>>>(pos);
    meta_kernel<<<MCL / 256, 256>>>(pos, batch,
                                    out + baseOut,
                                    (int*)(out + baseOut + MCL * 3),
                                    writePos, writeBatch);
    knn_kernel<<<MCL / 32, 256>>>();
    gemm_kernel<<<dim3(NPTS / 64, COUT / 64), 256>>>(x, W, b);
    bn_part_kernel<<<256, 256>>>();
    bn_final_kernel<<<1, 256>>>(gamma, beta);
    gather_kernel<<<MCL, 256>>>(out);
}

// round 12
// speedup vs baseline: 1.0726x; 1.0726x over previous
#include <cuda_runtime.h>
#include <cuda_bf16.h>

// ============================================================================
// TransitionDown: FPS (M=8192 of N=32768) + kNN(16) + Linear+BN+ReLU + max-pool
// Output layout (float32): [out 8192x256][sub_pos 8192x3][sub_batch 8192]
// All arithmetic exact f32. FPS: R10 barrier.cluster skeleton + coordinate
// carrying + all-thread redundant cross reduce (no pos[] LDG, no tail sync).
// ============================================================================

#define NPTS   32768
#define CIN    128
#define COUT   256
#define KNN_K  16
#define MCL    8192

#define FPS_CTAS    8
#define FPS_THREADS 512
#define PPT         8   // points per thread: 8*512*8 = 32768

// ---------------- device scratch (static; no allocation allowed) ------------
__device__ float4 g_pos4[NPTS];            // {x,y,z, |p|^2} exact f32
__device__ int    g_idx[MCL];              // FPS-selected indices
__device__ int    g_nbr[MCL * KNN_K];      // kNN indices
__device__ float  g_h[NPTS * COUT];        // linear output (pre-BN)
__device__ float  g_psum[256 * COUT];
__device__ float  g_psumsq[256 * COUT];
__device__ float  g_scale[COUT];
__device__ float  g_shift[COUT];

// ---------------- small helpers ---------------------------------------------
__device__ __forceinline__ float finf() { return __int_as_float(0x7f800000); }
__device__ __forceinline__ float fninf() { return __int_as_float(0xff800000); }

__device__ __forceinline__ unsigned long long pk2(float a, float b) {
    unsigned long long r;
    asm("mov.b64 %0, {%1, %2};" : "=l"(r) : "f"(a), "f"(b));
    return r;
}
__device__ __forceinline__ void upk2(unsigned long long v, float& a, float& b) {
    asm("mov.b64 {%0, %1}, %2;" : "=f"(a), "=f"(b) : "l"(v));
}
__device__ __forceinline__ unsigned long long add2(unsigned long long a, unsigned long long b) {
    unsigned long long r;
    asm("add.rn.f32x2 %0, %1, %2;" : "=l"(r) : "l"(a), "l"(b));
    return r;
}
__device__ __forceinline__ unsigned long long mul2(unsigned long long a, unsigned long long b) {
    unsigned long long r;
    asm("mul.rn.f32x2 %0, %1, %2;" : "=l"(r) : "l"(a), "l"(b));
    return r;
}
// store u64 into the same smem offset of a peer CTA in the cluster
__device__ __forceinline__ void st_cluster_u64(unsigned laddr, unsigned rank,
                                               unsigned long long v) {
    asm volatile(
        "{\n\t"
        ".reg .b32 ra;\n\t"
        "mapa.shared::cluster.u32 ra, %0, %1;\n\t"
        "st.shared::cluster.u64 [ra], %2;\n\t"
        "}"
        :: "r"(laddr), "r"(rank), "l"(v) : "memory");
}
__device__ __forceinline__ unsigned cluster_rank() {
    unsigned r;
    asm("mov.u32 %0, %%cluster_ctarank;" : "=r"(r));
    return r;
}

// ============================================================================
// 0) prep: pos4 table {x,y,z, |p|^2} exact f32
// ============================================================================
__global__ void prep_kernel(const float* __restrict__ pos) {
    int i = blockIdx.x * blockDim.x + threadIdx.x;
    if (i >= NPTS) return;
    float x = pos[3 * i + 0];
    float y = pos[3 * i + 1];
    float z = pos[3 * i + 2];
    float n = __fadd_rn(__fadd_rn(__fmul_rn(x, x), __fmul_rn(y, y)), __fmul_rn(z, z));
    g_pos4[i] = make_float4(x, y, z, n);
}

// ============================================================================
// 1) FPS: 8-CTA cluster, points register-resident, 1 barrier.cluster/round.
//    Exact f32, reference op order ((dx2+dy2)+dz2); argmax key packs
//    (dist_bits<<32)|(~idx) -> first-index tie like jnp.argmax.
//
//    Round: compute -> warp bfly argmax -> owner lane writes {key,xy,z} slot
//    -> syncthreads -> warp0 reduces 16 slots, lanes 0-7 push winner
//    {key,xy,z} to every CTA's cross[par] via DSMEM -> barrier.cluster
//    (arrive=release orders the remote stores; wait=acquire) -> ALL threads
//    redundantly reduce the 8 cross slots -> center in registers. No pos[]
//    LDG, no tid0 serial section, no tail __syncthreads.
//
//    Buffer safety: wslots/cross are parity double-buffered. The per-round
//    cluster barrier bounds cross-CTA skew to 1 round; the mid-round
//    __syncthreads bounds intra-CTA warp skew, so a buffer's round-(it+2)
//    write happens-after every round-it read of that buffer.
// ============================================================================
__global__ void __cluster_dims__(FPS_CTAS, 1, 1) __launch_bounds__(FPS_THREADS, 1)
fps_kernel(const float* __restrict__ pos) {
    // slot layout: [key, xy, z] per entry (24B; broadcast reads, no conflicts)
    __shared__ unsigned long long s_wslots[2][16][3];
    __shared__ unsigned long long s_cross[2][FPS_CTAS][3];

    const int tid = threadIdx.x;
    const int lane = tid & 31;
    const int wid = tid >> 5;
    const unsigned rank = cluster_rank();
    const int p0 = (int)(rank * FPS_THREADS + tid) * PPT;

    const unsigned cross_base = (unsigned)__cvta_generic_to_shared(&s_cross[0][0][0]);

    unsigned long long X[PPT / 2], Y[PPT / 2], Z[PPT / 2];
    float md[PPT];
#pragma unroll
    for (int pr = 0; pr < PPT / 2; ++pr) {
        int a = p0 + 2 * pr, b = a + 1;
        X[pr] = pk2(pos[3 * a + 0], pos[3 * b + 0]);
        Y[pr] = pk2(pos[3 * a + 1], pos[3 * b + 1]);
        Z[pr] = pk2(pos[3 * a + 2], pos[3 * b + 2]);
    }
#pragma unroll
    for (int j = 0; j < PPT; ++j) md[j] = finf();

    float cx = pos[0], cy = pos[1], cz = pos[2];
    if (rank == 0 && tid == 0) g_idx[0] = 0;

    for (int it = 1; it < MCL; ++it) {
        const int par = it & 1;
        unsigned long long ncx = pk2(-cx, -cx);
        unsigned long long ncy = pk2(-cy, -cy);
        unsigned long long ncz = pk2(-cz, -cz);

        float bv = fninf();
        int bi = p0;
#pragma unroll
        for (int pr = 0; pr < PPT / 2; ++pr) {
            unsigned long long ax = add2(X[pr], ncx);   // p + (-c) == p - c (IEEE-exact)
            unsigned long long ay = add2(Y[pr], ncy);
            unsigned long long az = add2(Z[pr], ncz);
            unsigned long long sx = mul2(ax, ax);
            unsigned long long sy = mul2(ay, ay);
            unsigned long long sz = mul2(az, az);
            unsigned long long s = add2(add2(sx, sy), sz);  // (dx2+dy2)+dz2
            float d0, d1;
            upk2(s, d0, d1);
            float m0 = fminf(md[2 * pr + 0], d0);
            md[2 * pr + 0] = m0;
            if (m0 > bv) { bv = m0; bi = p0 + 2 * pr + 0; }   // strict >: first idx wins
            float m1 = fminf(md[2 * pr + 1], d1);
            md[2 * pr + 1] = m1;
            if (m1 > bv) { bv = m1; bi = p0 + 2 * pr + 1; }
        }

        unsigned long long key =
            ((unsigned long long)__float_as_uint(bv) << 32) |
            (unsigned)(0xFFFFFFFFu - (unsigned)bi);
        // butterfly: every lane ends with the warp max (owner self-identifies)
#pragma unroll
        for (int o = 16; o > 0; o >>= 1) {
            unsigned long long k2 = __shfl_xor_sync(0xFFFFFFFFu, key, o);
            if (k2 > key) key = k2;
        }
        unsigned wbi = 0xFFFFFFFFu - (unsigned)key;
        int owner = (int)((wbi >> 3) & 31u);
        if (lane == owner) {
            int j = (int)(wbi & 7u);
            float px = 0.f, py = 0.f, pz = 0.f;
#pragma unroll
            for (int pr = 0; pr < PPT / 2; ++pr) {
                float a, b; upk2(X[pr], a, b);
                float c, d; upk2(Y[pr], c, d);
                float e, f; upk2(Z[pr], e, f);
                if ((j >> 1) == pr) {
                    px = (j & 1) ? b : a;
                    py = (j & 1) ? d : c;
                    pz = (j & 1) ? f : e;
                }
            }
            s_wslots[par][wid][0] = key;
            s_wslots[par][wid][1] = pk2(px, py);
            s_wslots[par][wid][2] = pk2(pz, 0.0f);
        }
        __syncthreads();

        if (wid == 0) {
            // reduce the 16 warp slots (lanes 16-31 mirror 0-15; max unaffected)
            unsigned long long k = s_wslots[par][lane & 15][0];
#pragma unroll
            for (int o = 16; o > 0; o >>= 1) {
                unsigned long long k2 = __shfl_xor_sync(0xFFFFFFFFu, k, o);
                if (k2 > k) k = k2;
            }
            unsigned wbi2 = 0xFFFFFFFFu - (unsigned)k;
            int w = (int)(((wbi2 >> 3) & 511u) >> 5);  // winning warp in this CTA
            unsigned long long xy = s_wslots[par][w][1];
            unsigned long long zz = s_wslots[par][w][2];
            if (lane < FPS_CTAS) {
                unsigned base = cross_base +
                                (unsigned)((par * FPS_CTAS + (int)rank) * 3) * 8u;
                st_cluster_u64(base + 0, (unsigned)lane, k);
                st_cluster_u64(base + 8, (unsigned)lane, xy);
                st_cluster_u64(base + 16, (unsigned)lane, zz);
            }
        }

        // arrive releases the remote stores; wait acquires peers' stores
        asm volatile("barrier.cluster.arrive.aligned;" ::: "memory");
        asm volatile("barrier.cluster.wait.aligned;" ::: "memory");

        // every thread redundantly reduces the 8 cross keys -> new center
        unsigned long long g = s_cross[par][0][0];
        int rw = 0;
#pragma unroll
        for (int r = 1; r < FPS_CTAS; ++r) {
            unsigned long long k2 = s_cross[par][r][0];
            if (k2 > g) { g = k2; rw = r; }
        }
        float dummy;
        upk2(s_cross[par][rw][1], cx, cy);
        upk2(s_cross[par][rw][2], cz, dummy);
        if (rank == 0 && tid == 0)
            g_idx[it] = (int)(0xFFFFFFFFu - (unsigned)g);
    }
}

// ============================================================================
// 2) meta: sub_pos / sub_batch outputs
// ============================================================================
__global__ void meta_kernel(const float* __restrict__ pos,
                            const int* __restrict__ batch,
                            float* outPos, int* outBatch,
                            int writePos, int writeBatch) {
    int m = blockIdx.x * blockDim.x + threadIdx.x;
    if (m >= MCL) return;
    int idx = g_idx[m];
    if (writePos) {
        outPos[3 * m + 0] = pos[3 * idx + 0];
        outPos[3 * m + 1] = pos[3 * idx + 1];
        outPos[3 * m + 2] = pos[3 * idx + 2];
    }
    if (writeBatch) outBatch[m] = batch[idx];
}

// ============================================================================
// 3) kNN: 8 lanes/query, smem-tiled pos4, register top-16, shuffle pop-merge.
//    d = (|q|^2 - 2*dot) + |p|^2, exact f32.
//    Merge key: total-order float encoding; ties break on global index.
// ============================================================================
#define KNN_TILE 2048
__global__ void __launch_bounds__(256) knn_kernel() {
    __shared__ float4 s_p[KNN_TILE];
    const int tid = threadIdx.x;
    const int q = blockIdx.x * 32 + (tid >> 3);
    const int s = tid & 7;

    const int ci = g_idx[q];
    const float4 qp = g_pos4[ci];

    float dist[KNN_K];
    int idn[KNN_K];
#pragma unroll
    for (int u = 0; u < KNN_K; ++u) { dist[u] = finf(); idn[u] = 0; }

    for (int t0 = 0; t0 < NPTS; t0 += KNN_TILE) {
        __syncthreads();
        for (int i = tid; i < KNN_TILE; i += 256) s_p[i] = g_pos4[t0 + i];
        __syncthreads();
        for (int t = s; t < KNN_TILE; t += 8) {
            float4 p = s_p[t];
            float dot = __fadd_rn(__fadd_rn(__fmul_rn(qp.x, p.x),
                                            __fmul_rn(qp.y, p.y)),
                                  __fmul_rn(qp.z, p.z));
            float d = __fadd_rn(__fsub_rn(qp.w, __fmul_rn(2.0f, dot)), p.w);
            if (d < dist[KNN_K - 1]) {
                dist[KNN_K - 1] = d;
                idn[KNN_K - 1] = t0 + t;
#pragma unroll
                for (int u = KNN_K - 1; u > 0; --u) {
                    if (dist[u] < dist[u - 1]) {
                        float td = dist[u]; dist[u] = dist[u - 1]; dist[u - 1] = td;
                        int ti = idn[u]; idn[u] = idn[u - 1]; idn[u - 1] = ti;
                    }
                }
            }
        }
    }

#pragma unroll 1
    for (int r = 0; r < KNN_K; ++r) {
        unsigned db = __float_as_uint(dist[0]);
        db = (db & 0x80000000u) ? ~db : (db | 0x80000000u);  // total order
        unsigned long long key =
            ((unsigned long long)db << 32) |
            (unsigned)((idn[0] << 3) | s);
#pragma unroll
        for (int o = 1; o < 8; o <<= 1) {
            unsigned long long k2 = __shfl_xor_sync(0xFFFFFFFFu, key, o, 8);
            if (k2 < key) key = k2;
        }
        int wl = (int)(key & 7u);
        int hid = (int)((key >> 3) & 0x7FFFu);
        if (s == 0) g_nbr[q * KNN_K + r] = hid;
        if (s == wl) {  // pop my head
#pragma unroll
            for (int u = 0; u < KNN_K - 1; ++u) {
                dist[u] = dist[u + 1];
                idn[u] = idn[u + 1];
            }
            dist[KNN_K - 1] = finf();
        }
    }
}

// ============================================================================
// 4) GEMM: h = x @ W + b, exact f32 FFMA, 64x64 tiles
// ============================================================================
__global__ void __launch_bounds__(256) gemm_kernel(const float* __restrict__ Xm,
                                                   const float* __restrict__ Wm,
                                                   const float* __restrict__ Bv) {
    __shared__ __align__(16) float As[32][72];  // A transposed [k][row], padded
    __shared__ __align__(16) float Bs[32][64];  // [k][col]

    const int tid = threadIdx.x;
    const int tx = tid & 15, ty = tid >> 4;
    const int r0 = blockIdx.x * 64;
    const int c0 = blockIdx.y * 64;

    float acc[4][4];
#pragma unroll
    for (int i = 0; i < 4; ++i)
#pragma unroll
        for (int j = 0; j < 4; ++j) acc[i][j] = 0.0f;

    for (int kc = 0; kc < CIN; kc += 32) {
        __syncthreads();
#pragma unroll
        for (int l = 0; l < 2; ++l) {  // A: 64 rows x 32 k = 512 float4
            int fi = tid * 2 + l;
            int row = fi >> 3;
            int kf = fi & 7;
            float4 a = *(const float4*)&Xm[(r0 + row) * CIN + kc + kf * 4];
            As[kf * 4 + 0][row] = a.x;
            As[kf * 4 + 1][row] = a.y;
            As[kf * 4 + 2][row] = a.z;
            As[kf * 4 + 3][row] = a.w;
        }
#pragma unroll
        for (int l = 0; l < 2; ++l) {  // B: 32 k x 64 cols = 512 float4
            int fi = tid * 2 + l;
            int kk = fi >> 4;
            int cf = fi & 15;
            *(float4*)&Bs[kk][cf * 4] =
                *(const float4*)&Wm[(kc + kk) * COUT + c0 + cf * 4];
        }
        __syncthreads();
#pragma unroll
        for (int kk = 0; kk < 32; ++kk) {
            float4 a = *(float4*)&As[kk][ty * 4];
            float4 b = *(float4*)&Bs[kk][tx * 4];
            float av[4] = {a.x, a.y, a.z, a.w};
            float bv[4] = {b.x, b.y, b.z, b.w};
#pragma unroll
            for (int i = 0; i < 4; ++i)
#pragma unroll
                for (int j = 0; j < 4; ++j) acc[i][j] = fmaf(av[i], bv[j], acc[i][j]);
        }
    }

    float4 bias = *(const float4*)&Bv[c0 + tx * 4];
#pragma unroll
    for (int i = 0; i < 4; ++i) {
        float4 o;
        o.x = acc[i][0] + bias.x;
        o.y = acc[i][1] + bias.y;
        o.z = acc[i][2] + bias.z;
        o.w = acc[i][3] + bias.w;
        *(float4*)&g_h[(r0 + ty * 4 + i) * COUT + c0 + tx * 4] = o;
    }
}

// ============================================================================
// 5) BatchNorm stats: deterministic two-stage tree (no float atomics)
// ============================================================================
__global__ void bn_part_kernel() {
    const int c = threadIdx.x;
    const int b = blockIdx.x;
    const float* hp = g_h + (size_t)b * 128 * COUT;
    float s = 0.0f, ss = 0.0f;
#pragma unroll 4
    for (int r = 0; r < 128; ++r) {
        float v = hp[r * COUT + c];
        s += v;
        ss = fmaf(v, v, ss);
    }
    g_psum[b * COUT + c] = s;
    g_psumsq[b * COUT + c] = ss;
}

__global__ void bn_final_kernel(const float* __restrict__ gamma,
                                const float* __restrict__ beta) {
    const int c = threadIdx.x;
    float s = 0.0f, ss = 0.0f;
    for (int b = 0; b < 256; ++b) {
        s += g_psum[b * COUT + c];
        ss += g_psumsq[b * COUT + c];
    }
    const float invN = 1.0f / (float)NPTS;
    float mu = s * invN;
    float var = ss * invN - mu * mu;
    var = fmaxf(var, 0.0f);
    float sc = gamma[c] * (1.0f / sqrtf(var + 1e-5f));
    g_scale[c] = sc;
    g_shift[c] = beta[c] - mu * sc;
}

// ============================================================================
// 6) gather-max with fused BN+ReLU per gathered element
// ============================================================================
__global__ void __launch_bounds__(256) gather_kernel(float* __restrict__ out) {
    const int m = blockIdx.x;
    const int c = threadIdx.x;
    const float sc = g_scale[c];
    const float sh = g_shift[c];
    float acc = fninf();
#pragma unroll
    for (int k = 0; k < KNN_K; ++k) {
        int id = g_nbr[m * KNN_K + k];
        float v = g_h[(size_t)id * COUT + c];
        float bn = fmaxf(fmaf(v, sc, sh), 0.0f);  // ReLU(BN(v))
        acc = fmaxf(acc, bn);
    }
    out[m * COUT + c] = acc;
}

// ============================================================================
// launch
// ============================================================================
extern "C" void kernel_launch(void* const* d_in, const int* in_sizes, int n_in,
                              void* d_out, int out_size) {
    const float* x     = (const float*)d_in[0];  // [32768,128]
    const float* pos   = (const float*)d_in[1];  // [32768,3]
    const int*   batch = (const int*)d_in[2];    // [32768]
    const float* W     = (const float*)d_in[3];  // [128,256]
    const float* b     = (const float*)d_in[4];  // [256]
    const float* gamma = (const float*)d_in[5];  // [256]
    const float* beta  = (const float*)d_in[6];  // [256]
    float* out = (float*)d_out;

    const int baseOut = MCL * COUT;              // 2097152
    const int writePos = (out_size >= baseOut + MCL * 3) ? 1 : 0;
    const int writeBatch = (out_size >= baseOut + MCL * 3 + MCL) ? 1 : 0;

    prep_kernel<<<NPTS / 256, 256>>>(pos);
    fps_kernel<<<FPS_CTAS, FPS_THREADS>>>(pos);
    meta_kernel<<<MCL / 256, 256>>>(pos, batch,
                                    out + baseOut,
                                    (int*)(out + baseOut + MCL * 3),
                                    writePos, writeBatch);
    knn_kernel<<<MCL / 32, 256>>>();
    gemm_kernel<<<dim3(NPTS / 64, COUT / 64), 256>>>(x, W, b);
    bn_part_kernel<<<256, 256>>>();
    bn_final_kernel<<<1, 256>>>(gamma, beta);
    gather_kernel<<<MCL, 256>>>(out);
}

// round 13
// speedup vs baseline: 1.1306x; 1.0540x over previous
#include <cuda_runtime.h>
#include <cuda_bf16.h>

// ============================================================================
// TransitionDown: FPS (M=8192 of N=32768) + kNN(16) + Linear+BN+ReLU + max-pool
// Output layout (float32): [out 8192x256][sub_pos 8192x3][sub_batch 8192]
// All arithmetic exact f32. FPS: cluster skeleton + REDUX reductions +
// branchless coordinate carrying (no pos[] LDG, no divergent extraction).
// ============================================================================

#define NPTS   32768
#define CIN    128
#define COUT   256
#define KNN_K  16
#define MCL    8192

#define FPS_CTAS    8
#define FPS_THREADS 512
#define PPT         8   // points per thread: 8*512*8 = 32768

// ---------------- device scratch (static; no allocation allowed) ------------
__device__ float4 g_pos4[NPTS];            // {x,y,z, |p|^2} exact f32
__device__ int    g_idx[MCL];              // FPS-selected indices
__device__ int    g_nbr[MCL * KNN_K];      // kNN indices
__device__ float  g_h[NPTS * COUT];        // linear output (pre-BN)
__device__ float  g_psum[256 * COUT];
__device__ float  g_psumsq[256 * COUT];
__device__ float  g_scale[COUT];
__device__ float  g_shift[COUT];

// ---------------- small helpers ---------------------------------------------
__device__ __forceinline__ float finf() { return __int_as_float(0x7f800000); }
__device__ __forceinline__ float fninf() { return __int_as_float(0xff800000); }

__device__ __forceinline__ unsigned long long pk2(float a, float b) {
    unsigned long long r;
    asm("mov.b64 %0, {%1, %2};" : "=l"(r) : "f"(a), "f"(b));
    return r;
}
__device__ __forceinline__ void upk2(unsigned long long v, float& a, float& b) {
    asm("mov.b64 {%0, %1}, %2;" : "=f"(a), "=f"(b) : "l"(v));
}
__device__ __forceinline__ unsigned long long add2(unsigned long long a, unsigned long long b) {
    unsigned long long r;
    asm("add.rn.f32x2 %0, %1, %2;" : "=l"(r) : "l"(a), "l"(b));
    return r;
}
__device__ __forceinline__ unsigned long long mul2(unsigned long long a, unsigned long long b) {
    unsigned long long r;
    asm("mul.rn.f32x2 %0, %1, %2;" : "=l"(r) : "l"(a), "l"(b));
    return r;
}
// store u64 into the same smem offset of a peer CTA in the cluster
__device__ __forceinline__ void st_cluster_u64(unsigned laddr, unsigned rank,
                                               unsigned long long v) {
    asm volatile(
        "{\n\t"
        ".reg .b32 ra;\n\t"
        "mapa.shared::cluster.u32 ra, %0, %1;\n\t"
        "st.shared::cluster.u64 [ra], %2;\n\t"
        "}"
        :: "r"(laddr), "r"(rank), "l"(v) : "memory");
}
__device__ __forceinline__ unsigned cluster_rank() {
    unsigned r;
    asm("mov.u32 %0, %%cluster_ctarank;" : "=r"(r));
    return r;
}

// ============================================================================
// 0) prep: pos4 table {x,y,z, |p|^2} exact f32
// ============================================================================
__global__ void prep_kernel(const float* __restrict__ pos) {
    int i = blockIdx.x * blockDim.x + threadIdx.x;
    if (i >= NPTS) return;
    float x = pos[3 * i + 0];
    float y = pos[3 * i + 1];
    float z = pos[3 * i + 2];
    float n = __fadd_rn(__fadd_rn(__fmul_rn(x, x), __fmul_rn(y, y)), __fmul_rn(z, z));
    g_pos4[i] = make_float4(x, y, z, n);
}

// ============================================================================
// 1) FPS: 8-CTA cluster, points register-resident, 1 barrier.cluster/round.
//    Exact f32, reference op order ((dx2+dy2)+dz2).
//    Argmax: distances >= 0, so u32 bit order == value order. Warp winner via
//    REDUX(dist_bits) then REDUX(~idx masked to matching lanes) -> exact
//    first-index tie-break like jnp.argmax. Winner's coords are extracted
//    branchlessly (j is warp-uniform) and carried through DSMEM, so the new
//    center never touches pos[] after init.
//
//    Buffer safety: wslots/cross are parity double-buffered; the per-round
//    cluster barrier bounds cross-CTA skew to 1 round and the mid-round
//    __syncthreads bounds intra-CTA skew, so a buffer's round-(it+2) write
//    happens-after every round-it read.
// ============================================================================
__global__ void __cluster_dims__(FPS_CTAS, 1, 1) __launch_bounds__(FPS_THREADS, 1)
fps_kernel(const float* __restrict__ pos) {
    // slot layout: [key, xy, z] per entry
    __shared__ unsigned long long s_wslots[2][16][3];
    __shared__ unsigned long long s_cross[2][FPS_CTAS][3];

    const int tid = threadIdx.x;
    const int lane = tid & 31;
    const int wid = tid >> 5;
    const unsigned rank = cluster_rank();
    const int p0 = (int)(rank * FPS_THREADS + tid) * PPT;

    const unsigned cross_base = (unsigned)__cvta_generic_to_shared(&s_cross[0][0][0]);

    unsigned long long X[PPT / 2], Y[PPT / 2], Z[PPT / 2];
    float md[PPT];
#pragma unroll
    for (int pr = 0; pr < PPT / 2; ++pr) {
        int a = p0 + 2 * pr, b = a + 1;
        X[pr] = pk2(pos[3 * a + 0], pos[3 * b + 0]);
        Y[pr] = pk2(pos[3 * a + 1], pos[3 * b + 1]);
        Z[pr] = pk2(pos[3 * a + 2], pos[3 * b + 2]);
    }
#pragma unroll
    for (int j = 0; j < PPT; ++j) md[j] = finf();

    float cx = pos[0], cy = pos[1], cz = pos[2];
    if (rank == 0 && tid == 0) g_idx[0] = 0;

    for (int it = 1; it < MCL; ++it) {
        const int par = it & 1;
        unsigned long long ncx = pk2(-cx, -cx);
        unsigned long long ncy = pk2(-cy, -cy);
        unsigned long long ncz = pk2(-cz, -cz);

        float bv = fninf();
        int bi = p0;
#pragma unroll
        for (int pr = 0; pr < PPT / 2; ++pr) {
            unsigned long long ax = add2(X[pr], ncx);   // p + (-c) == p - c (IEEE-exact)
            unsigned long long ay = add2(Y[pr], ncy);
            unsigned long long az = add2(Z[pr], ncz);
            unsigned long long sx = mul2(ax, ax);
            unsigned long long sy = mul2(ay, ay);
            unsigned long long sz = mul2(az, az);
            unsigned long long s = add2(add2(sx, sy), sz);  // (dx2+dy2)+dz2
            float d0, d1;
            upk2(s, d0, d1);
            float m0 = fminf(md[2 * pr + 0], d0);
            md[2 * pr + 0] = m0;
            if (m0 > bv) { bv = m0; bi = p0 + 2 * pr + 0; }   // strict >: first idx wins
            float m1 = fminf(md[2 * pr + 1], d1);
            md[2 * pr + 1] = m1;
            if (m1 > bv) { bv = m1; bi = p0 + 2 * pr + 1; }
        }

        // --- warp argmax via REDUX (dist >= 0 -> bit order == value order) ---
        unsigned bvb = __float_as_uint(bv);
        unsigned wmax = __reduce_max_sync(0xFFFFFFFFu, bvb);
        unsigned lowc = (bvb == wmax) ? (0xFFFFFFFFu - (unsigned)bi) : 0u;
        unsigned wlow = __reduce_max_sync(0xFFFFFFFFu, lowc);   // max ~idx == min idx
        unsigned wbi = 0xFFFFFFFFu - wlow;                      // warp-winning global idx

        // --- branchless coord extraction: j is warp-uniform; predicated store ---
        int owner = (int)((wbi >> 3) & 31u);
        int j = (int)(wbi & 7u);
        unsigned long long vx = (j & 4) ? ((j & 2) ? X[3] : X[2])
                                        : ((j & 2) ? X[1] : X[0]);
        unsigned long long vy = (j & 4) ? ((j & 2) ? Y[3] : Y[2])
                                        : ((j & 2) ? Y[1] : Y[0]);
        unsigned long long vz = (j & 4) ? ((j & 2) ? Z[3] : Z[2])
                                        : ((j & 2) ? Z[1] : Z[0]);
        float x0, x1, y0, y1, z0, z1;
        upk2(vx, x0, x1); upk2(vy, y0, y1); upk2(vz, z0, z1);
        float px = (j & 1) ? x1 : x0;
        float py = (j & 1) ? y1 : y0;
        float pz = (j & 1) ? z1 : z0;
        if (lane == owner) {
            s_wslots[par][wid][0] = ((unsigned long long)wmax << 32) | wlow;
            s_wslots[par][wid][1] = pk2(px, py);
            s_wslots[par][wid][2] = pk2(pz, 0.0f);
        }
        __syncthreads();

        if (wid == 0) {
            unsigned hi = 0u, lo = 0u;
            if (lane < 16) {
                unsigned long long k = s_wslots[par][lane][0];
                hi = (unsigned)(k >> 32);
                lo = (unsigned)k;
            }
            unsigned mhi = __reduce_max_sync(0xFFFFFFFFu, hi);
            unsigned lom = (hi == mhi) ? lo : 0u;
            unsigned mlo = __reduce_max_sync(0xFFFFFFFFu, lom);
            unsigned ball = __ballot_sync(0xFFFFFFFFu, (hi == mhi) && (lo == mlo) && (lane < 16));
            int w = __ffs(ball) - 1;   // winning slot index in this CTA
            if (lane < FPS_CTAS) {
                unsigned long long kk = ((unsigned long long)mhi << 32) | mlo;
                unsigned long long xy = s_wslots[par][w][1];
                unsigned long long zz = s_wslots[par][w][2];
                unsigned base = cross_base +
                                (unsigned)((par * FPS_CTAS + (int)rank) * 3) * 8u;
                st_cluster_u64(base + 0, (unsigned)lane, kk);
                st_cluster_u64(base + 8, (unsigned)lane, xy);
                st_cluster_u64(base + 16, (unsigned)lane, zz);
            }
        }

        // arrive releases the remote stores; wait acquires peers' stores
        asm volatile("barrier.cluster.arrive.aligned;" ::: "memory");
        asm volatile("barrier.cluster.wait.aligned;" ::: "memory");

        // every thread redundantly reduces the 8 cross keys -> new center
        unsigned long long g = s_cross[par][0][0];
        int rw = 0;
#pragma unroll
        for (int r = 1; r < FPS_CTAS; ++r) {
            unsigned long long k2 = s_cross[par][r][0];
            if (k2 > g) { g = k2; rw = r; }
        }
        float dummy;
        upk2(s_cross[par][rw][1], cx, cy);
        upk2(s_cross[par][rw][2], cz, dummy);
        if (rank == 0 && tid == 0)
            g_idx[it] = (int)(0xFFFFFFFFu - (unsigned)g);
    }
}

// ============================================================================
// 2) meta: sub_pos / sub_batch outputs
// ============================================================================
__global__ void meta_kernel(const float* __restrict__ pos,
                            const int* __restrict__ batch,
                            float* outPos, int* outBatch,
                            int writePos, int writeBatch) {
    int m = blockIdx.x * blockDim.x + threadIdx.x;
    if (m >= MCL) return;
    int idx = g_idx[m];
    if (writePos) {
        outPos[3 * m + 0] = pos[3 * idx + 0];
        outPos[3 * m + 1] = pos[3 * idx + 1];
        outPos[3 * m + 2] = pos[3 * idx + 2];
    }
    if (writeBatch) outBatch[m] = batch[idx];
}

// ============================================================================
// 3) kNN: 16 lanes/query, smem-tiled pos4, register top-16, shuffle pop-merge.
//    d = (|q|^2 - 2*dot) + |p|^2, exact f32.
//    Merge key: total-order float encoding; ties break on global index.
// ============================================================================
#define KNN_TILE 2048
#define LPQ      16
__global__ void __launch_bounds__(256) knn_kernel() {
    __shared__ float4 s_p[KNN_TILE];
    const int tid = threadIdx.x;
    const int q = blockIdx.x * (256 / LPQ) + (tid / LPQ);
    const int s = tid & (LPQ - 1);

    const int ci = g_idx[q];
    const float4 qp = g_pos4[ci];

    float dist[KNN_K];
    int idn[KNN_K];
#pragma unroll
    for (int u = 0; u < KNN_K; ++u) { dist[u] = finf(); idn[u] = 0; }

    for (int t0 = 0; t0 < NPTS; t0 += KNN_TILE) {
        __syncthreads();
        for (int i = tid; i < KNN_TILE; i += 256) s_p[i] = g_pos4[t0 + i];
        __syncthreads();
        for (int t = s; t < KNN_TILE; t += LPQ) {
            float4 p = s_p[t];
            float dot = __fadd_rn(__fadd_rn(__fmul_rn(qp.x, p.x),
                                            __fmul_rn(qp.y, p.y)),
                                  __fmul_rn(qp.z, p.z));
            float d = __fadd_rn(__fsub_rn(qp.w, __fmul_rn(2.0f, dot)), p.w);
            if (d < dist[KNN_K - 1]) {
                dist[KNN_K - 1] = d;
                idn[KNN_K - 1] = t0 + t;
#pragma unroll
                for (int u = KNN_K - 1; u > 0; --u) {
                    if (dist[u] < dist[u - 1]) {
                        float td = dist[u]; dist[u] = dist[u - 1]; dist[u - 1] = td;
                        int ti = idn[u]; idn[u] = idn[u - 1]; idn[u - 1] = ti;
                    }
                }
            }
        }
    }

#pragma unroll 1
    for (int r = 0; r < KNN_K; ++r) {
        unsigned db = __float_as_uint(dist[0]);
        db = (db & 0x80000000u) ? ~db : (db | 0x80000000u);  // total order
        unsigned long long key =
            ((unsigned long long)db << 32) |
            (unsigned)((idn[0] << 4) | s);
#pragma unroll
        for (int o = 1; o < LPQ; o <<= 1) {
            unsigned long long k2 = __shfl_xor_sync(0xFFFFFFFFu, key, o, LPQ);
            if (k2 < key) key = k2;
        }
        int wl = (int)(key & (LPQ - 1));
        int hid = (int)((key >> 4) & 0x7FFFu);
        if (s == 0) g_nbr[q * KNN_K + r] = hid;
        if (s == wl) {  // pop my head
#pragma unroll
            for (int u = 0; u < KNN_K - 1; ++u) {
                dist[u] = dist[u + 1];
                idn[u] = idn[u + 1];
            }
            dist[KNN_K - 1] = finf();
        }
    }
}

// ============================================================================
// 4) GEMM: h = x @ W + b, exact f32 FFMA, 64x64 tiles
// ============================================================================
__global__ void __launch_bounds__(256) gemm_kernel(const float* __restrict__ Xm,
                                                   const float* __restrict__ Wm,
                                                   const float* __restrict__ Bv) {
    __shared__ __align__(16) float As[32][72];  // A transposed [k][row], padded
    __shared__ __align__(16) float Bs[32][64];  // [k][col]

    const int tid = threadIdx.x;
    const int tx = tid & 15, ty = tid >> 4;
    const int r0 = blockIdx.x * 64;
    const int c0 = blockIdx.y * 64;

    float acc[4][4];
#pragma unroll
    for (int i = 0; i < 4; ++i)
#pragma unroll
        for (int j = 0; j < 4; ++j) acc[i][j] = 0.0f;

    for (int kc = 0; kc < CIN; kc += 32) {
        __syncthreads();
#pragma unroll
        for (int l = 0; l < 2; ++l) {  // A: 64 rows x 32 k = 512 float4
            int fi = tid * 2 + l;
            int row = fi >> 3;
            int kf = fi & 7;
            float4 a = *(const float4*)&Xm[(r0 + row) * CIN + kc + kf * 4];
            As[kf * 4 + 0][row] = a.x;
            As[kf * 4 + 1][row] = a.y;
            As[kf * 4 + 2][row] = a.z;
            As[kf * 4 + 3][row] = a.w;
        }
#pragma unroll
        for (int l = 0; l < 2; ++l) {  // B: 32 k x 64 cols = 512 float4
            int fi = tid * 2 + l;
            int kk = fi >> 4;
            int cf = fi & 15;
            *(float4*)&Bs[kk][cf * 4] =
                *(const float4*)&Wm[(kc + kk) * COUT + c0 + cf * 4];
        }
        __syncthreads();
#pragma unroll
        for (int kk = 0; kk < 32; ++kk) {
            float4 a = *(float4*)&As[kk][ty * 4];
            float4 b = *(float4*)&Bs[kk][tx * 4];
            float av[4] = {a.x, a.y, a.z, a.w};
            float bv[4] = {b.x, b.y, b.z, b.w};
#pragma unroll
            for (int i = 0; i < 4; ++i)
#pragma unroll
                for (int j = 0; j < 4; ++j) acc[i][j] = fmaf(av[i], bv[j], acc[i][j]);
        }
    }

    float4 bias = *(const float4*)&Bv[c0 + tx * 4];
#pragma unroll
    for (int i = 0; i < 4; ++i) {
        float4 o;
        o.x = acc[i][0] + bias.x;
        o.y = acc[i][1] + bias.y;
        o.z = acc[i][2] + bias.z;
        o.w = acc[i][3] + bias.w;
        *(float4*)&g_h[(r0 + ty * 4 + i) * COUT + c0 + tx * 4] = o;
    }
}

// ============================================================================
// 5) BatchNorm stats: deterministic two-stage tree (no float atomics)
// ============================================================================
__global__ void bn_part_kernel() {
    const int c = threadIdx.x;
    const int b = blockIdx.x;
    const float* hp = g_h + (size_t)b * 128 * COUT;
    float s = 0.0f, ss = 0.0f;
#pragma unroll 4
    for (int r = 0; r < 128; ++r) {
        float v = hp[r * COUT + c];
        s += v;
        ss = fmaf(v, v, ss);
    }
    g_psum[b * COUT + c] = s;
    g_psumsq[b * COUT + c] = ss;
}

__global__ void bn_final_kernel(const float* __restrict__ gamma,
                                const float* __restrict__ beta) {
    const int c = threadIdx.x;
    float s = 0.0f, ss = 0.0f;
    for (int b = 0; b < 256; ++b) {
        s += g_psum[b * COUT + c];
        ss += g_psumsq[b * COUT + c];
    }
    const float invN = 1.0f / (float)NPTS;
    float mu = s * invN;
    float var = ss * invN - mu * mu;
    var = fmaxf(var, 0.0f);
    float sc = gamma[c] * (1.0f / sqrtf(var + 1e-5f));
    g_scale[c] = sc;
    g_shift[c] = beta[c] - mu * sc;
}

// ============================================================================
// 6) gather-max with fused BN+ReLU per gathered element
// ============================================================================
__global__ void __launch_bounds__(256) gather_kernel(float* __restrict__ out) {
    const int m = blockIdx.x;
    const int c = threadIdx.x;
    const float sc = g_scale[c];
    const float sh = g_shift[c];
    float acc = fninf();
#pragma unroll
    for (int k = 0; k < KNN_K; ++k) {
        int id = g_nbr[m * KNN_K + k];
        float v = g_h[(size_t)id * COUT + c];
        float bn = fmaxf(fmaf(v, sc, sh), 0.0f);  // ReLU(BN(v))
        acc = fmaxf(acc, bn);
    }
    out[m * COUT + c] = acc;
}

// ============================================================================
// launch
// ============================================================================
extern "C" void kernel_launch(void* const* d_in, const int* in_sizes, int n_in,
                              void* d_out, int out_size) {
    const float* x     = (const float*)d_in[0];  // [32768,128]
    const float* pos   = (const float*)d_in[1];  // [32768,3]
    const int*   batch = (const int*)d_in[2];    // [32768]
    const float* W     = (const float*)d_in[3];  // [128,256]
    const float* b     = (const float*)d_in[4];  // [256]
    const float* gamma = (const float*)d_in[5];  // [256]
    const float* beta  = (const float*)d_in[6];  // [256]
    float* out = (float*)d_out;

    const int baseOut = MCL * COUT;              // 2097152
    const int writePos = (out_size >= baseOut + MCL * 3) ? 1 : 0;
    const int writeBatch = (out_size >= baseOut + MCL * 3 + MCL) ? 1 : 0;

    prep_kernel<<<NPTS / 256, 256>>>(pos);
    fps_kernel<<<FPS_CTAS, FPS_THREADS>>>(pos);
    meta_kernel<<<MCL / 256, 256>>>(pos, batch,
                                    out + baseOut,
                                    (int*)(out + baseOut + MCL * 3),
                                    writePos, writeBatch);
    knn_kernel<<<MCL / 16, 256>>>();
    gemm_kernel<<<dim3(NPTS / 64, COUT / 64), 256>>>(x, W, b);
    bn_part_kernel<<<256, 256>>>();
    bn_final_kernel<<<1, 256>>>(gamma, beta);
    gather_kernel<<<MCL, 256>>>(out);
}

// round 14
// speedup vs baseline: 1.2394x; 1.0962x over previous
#include <cuda_runtime.h>
#include <cuda_bf16.h>

// ============================================================================
// TransitionDown: FPS (M=8192 of N=32768) + kNN(16) + Linear+BN+ReLU + max-pool
// Output layout (float32): [out 8192x256][sub_pos 8192x3][sub_batch 8192]
// All arithmetic exact f32. FPS: spatial-bucket pruned (exact), 8-CTA cluster.
// ============================================================================

#define NPTS   32768
#define CIN    128
#define COUT   256
#define KNN_K  16
#define MCL    8192

#define FPS_CTAS    8
#define FPS_THREADS 512
#define PPT         8   // points per thread: 8*512*8 = 32768

#define NCELLS 4096     // 16^3 Morton grid

// ---------------- device scratch (static; no allocation allowed) ------------
__device__ float4  g_pos4[NPTS];           // {x,y,z, |p|^2} exact f32 (orig order)
__device__ float4  g_spos[NPTS];           // sorted {x,y,z, orig_idx bits}
__device__ int     g_cell[NPTS];           // cell id per point
__device__ int     g_hist[NCELLS];         // counts -> exclusive bases
__device__ int     g_coff[NCELLS];         // scatter cursors
__device__ unsigned g_benc[6];             // encoded bbox: min x,y,z ; max x,y,z
__device__ int     g_idx[MCL];             // FPS-selected indices (original ids)
__device__ int     g_nbr[MCL * KNN_K];     // kNN indices
__device__ float   g_h[NPTS * COUT];       // linear output (pre-BN)
__device__ float   g_psum[256 * COUT];
__device__ float   g_psumsq[256 * COUT];
__device__ float   g_scale[COUT];
__device__ float   g_shift[COUT];

// ---------------- small helpers ---------------------------------------------
__device__ __forceinline__ float finf() { return __int_as_float(0x7f800000); }
__device__ __forceinline__ float fninf() { return __int_as_float(0xff800000); }

__device__ __forceinline__ unsigned fenc(float f) {   // monotone float->u32
    unsigned b = __float_as_uint(f);
    return (b & 0x80000000u) ? ~b : (b | 0x80000000u);
}
__device__ __forceinline__ float fdec(unsigned e) {
    unsigned b = (e & 0x80000000u) ? (e & 0x7FFFFFFFu) : ~e;
    return __uint_as_float(b);
}

__device__ __forceinline__ unsigned long long pk2(float a, float b) {
    unsigned long long r;
    asm("mov.b64 %0, {%1, %2};" : "=l"(r) : "f"(a), "f"(b));
    return r;
}
__device__ __forceinline__ void upk2(unsigned long long v, float& a, float& b) {
    asm("mov.b64 {%0, %1}, %2;" : "=f"(a), "=f"(b) : "l"(v));
}
__device__ __forceinline__ unsigned long long add2(unsigned long long a, unsigned long long b) {
    unsigned long long r;
    asm("add.rn.f32x2 %0, %1, %2;" : "=l"(r) : "l"(a), "l"(b));
    return r;
}
__device__ __forceinline__ unsigned long long mul2(unsigned long long a, unsigned long long b) {
    unsigned long long r;
    asm("mul.rn.f32x2 %0, %1, %2;" : "=l"(r) : "l"(a), "l"(b));
    return r;
}
__device__ __forceinline__ void st_cluster_u64(unsigned laddr, unsigned rank,
                                               unsigned long long v) {
    asm volatile(
        "{\n\t"
        ".reg .b32 ra;\n\t"
        "mapa.shared::cluster.u32 ra, %0, %1;\n\t"
        "st.shared::cluster.u64 [ra], %2;\n\t"
        "}"
        :: "r"(laddr), "r"(rank), "l"(v) : "memory");
}
__device__ __forceinline__ unsigned cluster_rank() {
    unsigned r;
    asm("mov.u32 %0, %%cluster_ctarank;" : "=r"(r));
    return r;
}
__device__ __forceinline__ unsigned spread3(unsigned x) {   // 4-bit -> every 3rd bit
    return (x & 1u) | ((x & 2u) << 2) | ((x & 4u) << 4) | ((x & 8u) << 6);
}

// ============================================================================
// 0) prep: pos4 table {x,y,z, |p|^2} exact f32
// ============================================================================
__global__ void prep_kernel(const float* __restrict__ pos) {
    int i = blockIdx.x * blockDim.x + threadIdx.x;
    if (i >= NPTS) return;
    float x = pos[3 * i + 0];
    float y = pos[3 * i + 1];
    float z = pos[3 * i + 2];
    float n = __fadd_rn(__fadd_rn(__fmul_rn(x, x), __fmul_rn(y, y)), __fmul_rn(z, z));
    g_pos4[i] = make_float4(x, y, z, n);
}

// ============================================================================
// 0b) spatial binning: bbox -> cell ids + histogram -> prefix -> scatter.
//     Order inside a cell is atomic (nondeterministic) but FPS tie-breaks on
//     ORIGINAL index, so the final output is placement-invariant.
// ============================================================================
__global__ void binit_kernel() {
    int t = threadIdx.x;
    for (int k = t; k < NCELLS; k += 256) { g_hist[k] = 0; g_coff[k] = 0; }
    if (t < 3) g_benc[t] = 0xFFFFFFFFu;   // min slots (atomicMin on encoded)
    if (t >= 3 && t < 6) g_benc[t] = 0u;  // max slots (atomicMax on encoded)
}

__global__ void bbox_kernel(const float* __restrict__ pos) {
    int i = blockIdx.x * blockDim.x + threadIdx.x;
    unsigned ex = fenc(pos[3 * i + 0]);
    unsigned ey = fenc(pos[3 * i + 1]);
    unsigned ez = fenc(pos[3 * i + 2]);
    unsigned mnx = ~__reduce_max_sync(0xFFFFFFFFu, ~ex);
    unsigned mny = ~__reduce_max_sync(0xFFFFFFFFu, ~ey);
    unsigned mnz = ~__reduce_max_sync(0xFFFFFFFFu, ~ez);
    unsigned mxx = __reduce_max_sync(0xFFFFFFFFu, ex);
    unsigned mxy = __reduce_max_sync(0xFFFFFFFFu, ey);
    unsigned mxz = __reduce_max_sync(0xFFFFFFFFu, ez);
    if ((threadIdx.x & 31) == 0) {
        atomicMin(&g_benc[0], mnx); atomicMin(&g_benc[1], mny); atomicMin(&g_benc[2], mnz);
        atomicMax(&g_benc[3], mxx); atomicMax(&g_benc[4], mxy); atomicMax(&g_benc[5], mxz);
    }
}

__global__ void cell_kernel(const float* __restrict__ pos) {
    int i = blockIdx.x * blockDim.x + threadIdx.x;
    float mnx = fdec(g_benc[0]), mny = fdec(g_benc[1]), mnz = fdec(g_benc[2]);
    float mxx = fdec(g_benc[3]), mxy = fdec(g_benc[4]), mxz = fdec(g_benc[5]);
    float sx = 16.0f / fmaxf(mxx - mnx, 1e-20f);
    float sy = 16.0f / fmaxf(mxy - mny, 1e-20f);
    float sz = 16.0f / fmaxf(mxz - mnz, 1e-20f);
    int ix = min(15, max(0, (int)((pos[3 * i + 0] - mnx) * sx)));
    int iy = min(15, max(0, (int)((pos[3 * i + 1] - mny) * sy)));
    int iz = min(15, max(0, (int)((pos[3 * i + 2] - mnz) * sz)));
    int cell = (int)(spread3((unsigned)ix) | (spread3((unsigned)iy) << 1) |
                     (spread3((unsigned)iz) << 2));
    g_cell[i] = cell;
    atomicAdd(&g_hist[cell], 1);
}

__global__ void prefix_kernel() {   // 1 CTA, 256 threads: exclusive scan of 4096
    __shared__ int part[256];
    __shared__ int base[256];
    int t = threadIdx.x;
    int loc[16];
    int s = 0;
#pragma unroll
    for (int k = 0; k < 16; ++k) { loc[k] = s; s += g_hist[t * 16 + k]; }
    part[t] = s;
    __syncthreads();
    if (t == 0) {
        int acc = 0;
        for (int i = 0; i < 256; ++i) { base[i] = acc; acc += part[i]; }
    }
    __syncthreads();
#pragma unroll
    for (int k = 0; k < 16; ++k) g_hist[t * 16 + k] = base[t] + loc[k];
}

__global__ void scatter_kernel(const float* __restrict__ pos) {
    int i = blockIdx.x * blockDim.x + threadIdx.x;
    int cell = g_cell[i];
    int p = g_hist[cell] + atomicAdd(&g_coff[cell], 1);
    g_spos[p] = make_float4(pos[3 * i + 0], pos[3 * i + 1], pos[3 * i + 2],
                            __int_as_float(i));
}

// ============================================================================
// 1) FPS: 8-CTA cluster, bucket-pruned, 1 barrier.cluster/round.
//    Exact f32, reference op order ((dx2+dy2)+dz2). Each thread owns 8
//    spatially-adjacent points + bbox. Skip rule (exact): if
//    dmin2(center,bbox)*(1-1e-5) > max(md) then every computed d(p,c) > md[p]
//    (fp margin 5e-7 << 1e-5), so the fminf update is a no-op -> reuse key.
//    Argmax key = (md_bits<<32)|(~orig_idx) -> first-ORIGINAL-index ties,
//    matching jnp.argmax over the original point order.
// ============================================================================
__global__ void __cluster_dims__(FPS_CTAS, 1, 1) __launch_bounds__(FPS_THREADS, 1)
fps_kernel(const float* __restrict__ pos) {
    __shared__ unsigned long long s_wslots[2][16][3];   // [key, xy, z]
    __shared__ unsigned long long s_cross[2][FPS_CTAS][3];

    const int tid = threadIdx.x;
    const int lane = tid & 31;
    const int wid = tid >> 5;
    const unsigned rank = cluster_rank();
    const int p0 = (int)(rank * FPS_THREADS + tid) * PPT;

    const unsigned cross_base = (unsigned)__cvta_generic_to_shared(&s_cross[0][0][0]);

    unsigned long long X[PPT / 2], Y[PPT / 2], Z[PPT / 2];
    float md[PPT];
    int oi[PPT];
    float bxlo = finf(), bylo = finf(), bzlo = finf();
    float bxhi = fninf(), byhi = fninf(), bzhi = fninf();
#pragma unroll
    for (int j = 0; j < PPT; ++j) {
        float4 p = g_spos[p0 + j];
        oi[j] = __float_as_int(p.w);
        md[j] = finf();
        bxlo = fminf(bxlo, p.x); bxhi = fmaxf(bxhi, p.x);
        bylo = fminf(bylo, p.y); byhi = fmaxf(byhi, p.y);
        bzlo = fminf(bzlo, p.z); bzhi = fmaxf(bzhi, p.z);
        if (j & 1) {
            float4 q = g_spos[p0 + j - 1];
            X[j >> 1] = pk2(q.x, p.x);
            Y[j >> 1] = pk2(q.y, p.y);
            Z[j >> 1] = pk2(q.z, p.z);
        }
    }

    unsigned long long Bkey = ((unsigned long long)0x7f800000u << 32);  // md=inf
    int jwin = 0;

    float cx = pos[0], cy = pos[1], cz = pos[2];
    if (rank == 0 && tid == 0) g_idx[0] = 0;

    for (int it = 1; it < MCL; ++it) {
        const int par = it & 1;

        // ---- exact bucket-prune test ----
        float Bval = __uint_as_float((unsigned)(Bkey >> 32));
        float ddx = fmaxf(fmaxf(bxlo - cx, cx - bxhi), 0.0f);
        float ddy = fmaxf(fmaxf(bylo - cy, cy - byhi), 0.0f);
        float ddz = fmaxf(fmaxf(bzlo - cz, cz - bzhi), 0.0f);
        float dmin2 = ddx * ddx + ddy * ddy + ddz * ddz;
        bool active = !(dmin2 * 0.99999f > Bval);

        if (active) {
            unsigned long long ncx = pk2(-cx, -cx);
            unsigned long long ncy = pk2(-cy, -cy);
            unsigned long long ncz = pk2(-cz, -cz);
#pragma unroll
            for (int pr = 0; pr < PPT / 2; ++pr) {
                unsigned long long ax = add2(X[pr], ncx);   // p + (-c) == p - c (exact)
                unsigned long long ay = add2(Y[pr], ncy);
                unsigned long long az = add2(Z[pr], ncz);
                unsigned long long sx = mul2(ax, ax);
                unsigned long long sy = mul2(ay, ay);
                unsigned long long sz = mul2(az, az);
                unsigned long long s = add2(add2(sx, sy), sz);  // (dx2+dy2)+dz2
                float d0, d1;
                upk2(s, d0, d1);
                md[2 * pr + 0] = fminf(md[2 * pr + 0], d0);
                md[2 * pr + 1] = fminf(md[2 * pr + 1], d1);
            }
            // rescan: max (md, ~orig_idx) key
            unsigned long long bk = 0ULL;
            int jw = 0;
#pragma unroll
            for (int j = 0; j < PPT; ++j) {
                unsigned long long k =
                    ((unsigned long long)__float_as_uint(md[j]) << 32) |
                    (unsigned)(0xFFFFFFFFu - (unsigned)oi[j]);
                if (k > bk) { bk = k; jw = j; }
            }
            Bkey = bk;
            jwin = jw;
        }

        // ---- warp argmax via REDUX (md >= 0 -> bit order == value order) ----
        unsigned bvb = (unsigned)(Bkey >> 32);
        unsigned mylo = (unsigned)Bkey;
        unsigned wmax = __reduce_max_sync(0xFFFFFFFFu, bvb);
        unsigned lowc = (bvb == wmax) ? mylo : 0u;
        unsigned wlow = __reduce_max_sync(0xFFFFFFFFu, lowc);   // max ~idx == min idx
        unsigned ball = __ballot_sync(0xFFFFFFFFu, (bvb == wmax) && (mylo == wlow));
        int owner = __ffs(ball) - 1;

        // ---- branchless coord extraction from own jwin; predicated store ----
        int j = jwin;
        unsigned long long vx = (j & 4) ? ((j & 2) ? X[3] : X[2])
                                        : ((j & 2) ? X[1] : X[0]);
        unsigned long long vy = (j & 4) ? ((j & 2) ? Y[3] : Y[2])
                                        : ((j & 2) ? Y[1] : Y[0]);
        unsigned long long vz = (j & 4) ? ((j & 2) ? Z[3] : Z[2])
                                        : ((j & 2) ? Z[1] : Z[0]);
        float x0, x1, y0, y1, z0, z1;
        upk2(vx, x0, x1); upk2(vy, y0, y1); upk2(vz, z0, z1);
        float px = (j & 1) ? x1 : x0;
        float py = (j & 1) ? y1 : y0;
        float pz = (j & 1) ? z1 : z0;
        if (lane == owner) {
            s_wslots[par][wid][0] = ((unsigned long long)wmax << 32) | wlow;
            s_wslots[par][wid][1] = pk2(px, py);
            s_wslots[par][wid][2] = pk2(pz, 0.0f);
        }
        __syncthreads();

        if (wid == 0) {
            unsigned hi = 0u, lo = 0u;
            if (lane < 16) {
                unsigned long long k = s_wslots[par][lane][0];
                hi = (unsigned)(k >> 32);
                lo = (unsigned)k;
            }
            unsigned mhi = __reduce_max_sync(0xFFFFFFFFu, hi);
            unsigned lom = (hi == mhi) ? lo : 0u;
            unsigned mlo = __reduce_max_sync(0xFFFFFFFFu, lom);
            unsigned b2 = __ballot_sync(0xFFFFFFFFu,
                                        (hi == mhi) && (lo == mlo) && (lane < 16));
            int w = __ffs(b2) - 1;
            if (lane < FPS_CTAS) {
                unsigned long long kk = ((unsigned long long)mhi << 32) | mlo;
                unsigned long long xy = s_wslots[par][w][1];
                unsigned long long zz = s_wslots[par][w][2];
                unsigned base = cross_base +
                                (unsigned)((par * FPS_CTAS + (int)rank) * 3) * 8u;
                st_cluster_u64(base + 0, (unsigned)lane, kk);
                st_cluster_u64(base + 8, (unsigned)lane, xy);
                st_cluster_u64(base + 16, (unsigned)lane, zz);
            }
        }

        asm volatile("barrier.cluster.arrive.aligned;" ::: "memory");
        asm volatile("barrier.cluster.wait.aligned;" ::: "memory");

        // every thread redundantly reduces the 8 cross keys -> new center
        unsigned long long g = s_cross[par][0][0];
        int rw = 0;
#pragma unroll
        for (int r = 1; r < FPS_CTAS; ++r) {
            unsigned long long k2 = s_cross[par][r][0];
            if (k2 > g) { g = k2; rw = r; }
        }
        float dummy;
        upk2(s_cross[par][rw][1], cx, cy);
        upk2(s_cross[par][rw][2], cz, dummy);
        if (rank == 0 && tid == 0)
            g_idx[it] = (int)(0xFFFFFFFFu - (unsigned)g);
    }
}

// ============================================================================
// 2) meta: sub_pos / sub_batch outputs
// ============================================================================
__global__ void meta_kernel(const float* __restrict__ pos,
                            const int* __restrict__ batch,
                            float* outPos, int* outBatch,
                            int writePos, int writeBatch) {
    int m = blockIdx.x * blockDim.x + threadIdx.x;
    if (m >= MCL) return;
    int idx = g_idx[m];
    if (writePos) {
        outPos[3 * m + 0] = pos[3 * idx + 0];
        outPos[3 * m + 1] = pos[3 * idx + 1];
        outPos[3 * m + 2] = pos[3 * idx + 2];
    }
    if (writeBatch) outBatch[m] = batch[idx];
}

// ============================================================================
// 3) kNN: 8 lanes/query (measured best), smem-tiled pos4, register top-16,
//    shuffle pop-merge. d = (|q|^2 - 2*dot) + |p|^2, exact f32.
// ============================================================================
#define KNN_TILE 2048
__global__ void __launch_bounds__(256) knn_kernel() {
    __shared__ float4 s_p[KNN_TILE];
    const int tid = threadIdx.x;
    const int q = blockIdx.x * 32 + (tid >> 3);
    const int s = tid & 7;

    const int ci = g_idx[q];
    const float4 qp = g_pos4[ci];

    float dist[KNN_K];
    int idn[KNN_K];
#pragma unroll
    for (int u = 0; u < KNN_K; ++u) { dist[u] = finf(); idn[u] = 0; }

    for (int t0 = 0; t0 < NPTS; t0 += KNN_TILE) {
        __syncthreads();
        for (int i = tid; i < KNN_TILE; i += 256) s_p[i] = g_pos4[t0 + i];
        __syncthreads();
        for (int t = s; t < KNN_TILE; t += 8) {
            float4 p = s_p[t];
            float dot = __fadd_rn(__fadd_rn(__fmul_rn(qp.x, p.x),
                                            __fmul_rn(qp.y, p.y)),
                                  __fmul_rn(qp.z, p.z));
            float d = __fadd_rn(__fsub_rn(qp.w, __fmul_rn(2.0f, dot)), p.w);
            if (d < dist[KNN_K - 1]) {
                dist[KNN_K - 1] = d;
                idn[KNN_K - 1] = t0 + t;
#pragma unroll
                for (int u = KNN_K - 1; u > 0; --u) {
                    if (dist[u] < dist[u - 1]) {
                        float td = dist[u]; dist[u] = dist[u - 1]; dist[u - 1] = td;
                        int ti = idn[u]; idn[u] = idn[u - 1]; idn[u - 1] = ti;
                    }
                }
            }
        }
    }

#pragma unroll 1
    for (int r = 0; r < KNN_K; ++r) {
        unsigned db = __float_as_uint(dist[0]);
        db = (db & 0x80000000u) ? ~db : (db | 0x80000000u);  // total order
        unsigned long long key =
            ((unsigned long long)db << 32) |
            (unsigned)((idn[0] << 3) | s);
#pragma unroll
        for (int o = 1; o < 8; o <<= 1) {
            unsigned long long k2 = __shfl_xor_sync(0xFFFFFFFFu, key, o, 8);
            if (k2 < key) key = k2;
        }
        int wl = (int)(key & 7u);
        int hid = (int)((key >> 3) & 0x7FFFu);
        if (s == 0) g_nbr[q * KNN_K + r] = hid;
        if (s == wl) {  // pop my head
#pragma unroll
            for (int u = 0; u < KNN_K - 1; ++u) {
                dist[u] = dist[u + 1];
                idn[u] = idn[u + 1];
            }
            dist[KNN_K - 1] = finf();
        }
    }
}

// ============================================================================
// 4) GEMM: h = x @ W + b, exact f32 FFMA, 64x64 tiles
// ============================================================================
__global__ void __launch_bounds__(256) gemm_kernel(const float* __restrict__ Xm,
                                                   const float* __restrict__ Wm,
                                                   const float* __restrict__ Bv) {
    __shared__ __align__(16) float As[32][72];
    __shared__ __align__(16) float Bs[32][64];

    const int tid = threadIdx.x;
    const int tx = tid & 15, ty = tid >> 4;
    const int r0 = blockIdx.x * 64;
    const int c0 = blockIdx.y * 64;

    float acc[4][4];
#pragma unroll
    for (int i = 0; i < 4; ++i)
#pragma unroll
        for (int j = 0; j < 4; ++j) acc[i][j] = 0.0f;

    for (int kc = 0; kc < CIN; kc += 32) {
        __syncthreads();
#pragma unroll
        for (int l = 0; l < 2; ++l) {
            int fi = tid * 2 + l;
            int row = fi >> 3;
            int kf = fi & 7;
            float4 a = *(const float4*)&Xm[(r0 + row) * CIN + kc + kf * 4];
            As[kf * 4 + 0][row] = a.x;
            As[kf * 4 + 1][row] = a.y;
            As[kf * 4 + 2][row] = a.z;
            As[kf * 4 + 3][row] = a.w;
        }
#pragma unroll
        for (int l = 0; l < 2; ++l) {
            int fi = tid * 2 + l;
            int kk = fi >> 4;
            int cf = fi & 15;
            *(float4*)&Bs[kk][cf * 4] =
                *(const float4*)&Wm[(kc + kk) * COUT + c0 + cf * 4];
        }
        __syncthreads();
#pragma unroll
        for (int kk = 0; kk < 32; ++kk) {
            float4 a = *(float4*)&As[kk][ty * 4];
            float4 b = *(float4*)&Bs[kk][tx * 4];
            float av[4] = {a.x, a.y, a.z, a.w};
            float bv[4] = {b.x, b.y, b.z, b.w};
#pragma unroll
            for (int i = 0; i < 4; ++i)
#pragma unroll
                for (int j = 0; j < 4; ++j) acc[i][j] = fmaf(av[i], bv[j], acc[i][j]);
        }
    }

    float4 bias = *(const float4*)&Bv[c0 + tx * 4];
#pragma unroll
    for (int i = 0; i < 4; ++i) {
        float4 o;
        o.x = acc[i][0] + bias.x;
        o.y = acc[i][1] + bias.y;
        o.z = acc[i][2] + bias.z;
        o.w = acc[i][3] + bias.w;
        *(float4*)&g_h[(r0 + ty * 4 + i) * COUT + c0 + tx * 4] = o;
    }
}

// ============================================================================
// 5) BatchNorm stats: deterministic two-stage tree (no float atomics)
// ============================================================================
__global__ void bn_part_kernel() {
    const int c = threadIdx.x;
    const int b = blockIdx.x;
    const float* hp = g_h + (size_t)b * 128 * COUT;
    float s = 0.0f, ss = 0.0f;
#pragma unroll 4
    for (int r = 0; r < 128; ++r) {
        float v = hp[r * COUT + c];
        s += v;
        ss = fmaf(v, v, ss);
    }
    g_psum[b * COUT + c] = s;
    g_psumsq[b * COUT + c] = ss;
}

__global__ void bn_final_kernel(const float* __restrict__ gamma,
                                const float* __restrict__ beta) {
    const int c = threadIdx.x;
    float s = 0.0f, ss = 0.0f;
    for (int b = 0; b < 256; ++b) {
        s += g_psum[b * COUT + c];
        ss += g_psumsq[b * COUT + c];
    }
    const float invN = 1.0f / (float)NPTS;
    float mu = s * invN;
    float var = ss * invN - mu * mu;
    var = fmaxf(var, 0.0f);
    float sc = gamma[c] * (1.0f / sqrtf(var + 1e-5f));
    g_scale[c] = sc;
    g_shift[c] = beta[c] - mu * sc;
}

// ============================================================================
// 6) gather-max with fused BN+ReLU per gathered element
// ============================================================================
__global__ void __launch_bounds__(256) gather_kernel(float* __restrict__ out) {
    const int m = blockIdx.x;
    const int c = threadIdx.x;
    const float sc = g_scale[c];
    const float sh = g_shift[c];
    float acc = fninf();
#pragma unroll
    for (int k = 0; k < KNN_K; ++k) {
        int id = g_nbr[m * KNN_K + k];
        float v = g_h[(size_t)id * COUT + c];
        float bn = fmaxf(fmaf(v, sc, sh), 0.0f);
        acc = fmaxf(acc, bn);
    }
    out[m * COUT + c] = acc;
}

// ============================================================================
// launch
// ============================================================================
extern "C" void kernel_launch(void* const* d_in, const int* in_sizes, int n_in,
                              void* d_out, int out_size) {
    const float* x     = (const float*)d_in[0];  // [32768,128]
    const float* pos   = (const float*)d_in[1];  // [32768,3]
    const int*   batch = (const int*)d_in[2];    // [32768]
    const float* W     = (const float*)d_in[3];  // [128,256]
    const float* b     = (const float*)d_in[4];  // [256]
    const float* gamma = (const float*)d_in[5];  // [256]
    const float* beta  = (const float*)d_in[6];  // [256]
    float* out = (float*)d_out;

    const int baseOut = MCL * COUT;              // 2097152
    const int writePos = (out_size >= baseOut + MCL * 3) ? 1 : 0;
    const int writeBatch = (out_size >= baseOut + MCL * 3 + MCL) ? 1 : 0;

    prep_kernel<<<NPTS / 256, 256>>>(pos);
    binit_kernel<<<1, 256>>>();
    bbox_kernel<<<NPTS / 256, 256>>>(pos);
    cell_kernel<<<NPTS / 256, 256>>>(pos);
    prefix_kernel<<<1, 256>>>();
    scatter_kernel<<<NPTS / 256, 256>>>(pos);
    fps_kernel<<<FPS_CTAS, FPS_THREADS>>>(pos);
    meta_kernel<<<MCL / 256, 256>>>(pos, batch,
                                    out + baseOut,
                                    (int*)(out + baseOut + MCL * 3),
                                    writePos, writeBatch);
    knn_kernel<<<MCL / 32, 256>>>();
    gemm_kernel<<<dim3(NPTS / 64, COUT / 64), 256>>>(x, W, b);
    bn_part_kernel<<<256, 256>>>();
    bn_final_kernel<<<1, 256>>>(gamma, beta);
    gather_kernel<<<MCL, 256>>>(out);
}

// round 15
// speedup vs baseline: 1.2646x; 1.0204x over previous
#include <cuda_runtime.h>
#include <cuda_bf16.h>

// ============================================================================
// TransitionDown: FPS (M=8192 of N=32768) + kNN(16) + Linear+BN+ReLU + max-pool
// Output layout (float32): [out 8192x256][sub_pos 8192x3][sub_batch 8192]
// All arithmetic exact f32. FPS: bucket-pruned compute + single-warp mbarrier
// cluster rendezvous (two alternating barriers; no full-cluster barrier).
// ============================================================================

#define NPTS   32768
#define CIN    128
#define COUT   256
#define KNN_K  16
#define MCL    8192

#define FPS_CTAS    8
#define FPS_THREADS 512
#define PPT         8   // points per thread: 8*512*8 = 32768

#define NCELLS 4096     // 16^3 Morton grid

// ---------------- device scratch (static; no allocation allowed) ------------
__device__ float4  g_pos4[NPTS];           // {x,y,z, |p|^2} exact f32 (orig order)
__device__ float4  g_spos[NPTS];           // sorted {x,y,z, orig_idx bits}
__device__ int     g_cell[NPTS];           // cell id per point
__device__ int     g_hist[NCELLS];         // counts -> exclusive bases
__device__ int     g_coff[NCELLS];         // scatter cursors
__device__ unsigned g_benc[6];             // encoded bbox: min x,y,z ; max x,y,z
__device__ int     g_idx[MCL];             // FPS-selected indices (original ids)
__device__ int     g_nbr[MCL * KNN_K];     // kNN indices
__device__ float   g_h[NPTS * COUT];       // linear output (pre-BN)
__device__ float   g_psum[256 * COUT];
__device__ float   g_psumsq[256 * COUT];
__device__ float   g_scale[COUT];
__device__ float   g_shift[COUT];

// ---------------- small helpers ---------------------------------------------
__device__ __forceinline__ float finf() { return __int_as_float(0x7f800000); }
__device__ __forceinline__ float fninf() { return __int_as_float(0xff800000); }

__device__ __forceinline__ unsigned fenc(float f) {   // monotone float->u32
    unsigned b = __float_as_uint(f);
    return (b & 0x80000000u) ? ~b : (b | 0x80000000u);
}
__device__ __forceinline__ float fdec(unsigned e) {
    unsigned b = (e & 0x80000000u) ? (e & 0x7FFFFFFFu) : ~e;
    return __uint_as_float(b);
}

__device__ __forceinline__ unsigned long long pk2(float a, float b) {
    unsigned long long r;
    asm("mov.b64 %0, {%1, %2};" : "=l"(r) : "f"(a), "f"(b));
    return r;
}
__device__ __forceinline__ void upk2(unsigned long long v, float& a, float& b) {
    asm("mov.b64 {%0, %1}, %2;" : "=f"(a), "=f"(b) : "l"(v));
}
__device__ __forceinline__ unsigned long long add2(unsigned long long a, unsigned long long b) {
    unsigned long long r;
    asm("add.rn.f32x2 %0, %1, %2;" : "=l"(r) : "l"(a), "l"(b));
    return r;
}
__device__ __forceinline__ unsigned long long mul2(unsigned long long a, unsigned long long b) {
    unsigned long long r;
    asm("mul.rn.f32x2 %0, %1, %2;" : "=l"(r) : "l"(a), "l"(b));
    return r;
}
__device__ __forceinline__ void st_cluster_u64(unsigned laddr, unsigned rank,
                                               unsigned long long v) {
    asm volatile(
        "{\n\t"
        ".reg .b32 ra;\n\t"
        "mapa.shared::cluster.u32 ra, %0, %1;\n\t"
        "st.shared::cluster.u64 [ra], %2;\n\t"
        "}"
        :: "r"(laddr), "r"(rank), "l"(v) : "memory");
}
// arrive (release, cluster scope) on the mbarrier at the same offset in CTA `rank`
__device__ __forceinline__ void mbar_arrive_remote(unsigned local_mbar, unsigned rank) {
    asm volatile(
        "{\n\t"
        ".reg .b32 ra;\n\t"
        "mapa.shared::cluster.u32 ra, %0, %1;\n\t"
        "mbarrier.arrive.release.cluster.shared::cluster.b64 _, [ra];\n\t"
        "}"
        :: "r"(local_mbar), "r"(rank) : "memory");
}
__device__ __forceinline__ void mbar_wait_cluster(unsigned addr, unsigned parity) {
    unsigned done;
    asm volatile(
        "{\n\t.reg .pred p;\n\t"
        "mbarrier.try_wait.parity.acquire.cluster.shared::cta.b64 p, [%1], %2;\n\t"
        "selp.b32 %0, 1, 0, p;\n\t}"
        : "=r"(done) : "r"(addr), "r"(parity) : "memory");
    while (!done) {
        asm volatile(
            "{\n\t.reg .pred p;\n\t"
            "mbarrier.try_wait.parity.acquire.cluster.shared::cta.b64 p, [%1], %2;\n\t"
            "selp.b32 %0, 1, 0, p;\n\t}"
            : "=r"(done) : "r"(addr), "r"(parity) : "memory");
    }
}
__device__ __forceinline__ unsigned cluster_rank() {
    unsigned r;
    asm("mov.u32 %0, %%cluster_ctarank;" : "=r"(r));
    return r;
}
__device__ __forceinline__ unsigned spread3(unsigned x) {   // 4-bit -> every 3rd bit
    return (x & 1u) | ((x & 2u) << 2) | ((x & 4u) << 4) | ((x & 8u) << 6);
}

// ============================================================================
// 0) prep: pos4 table {x,y,z, |p|^2} exact f32
// ============================================================================
__global__ void prep_kernel(const float* __restrict__ pos) {
    int i = blockIdx.x * blockDim.x + threadIdx.x;
    if (i >= NPTS) return;
    float x = pos[3 * i + 0];
    float y = pos[3 * i + 1];
    float z = pos[3 * i + 2];
    float n = __fadd_rn(__fadd_rn(__fmul_rn(x, x), __fmul_rn(y, y)), __fmul_rn(z, z));
    g_pos4[i] = make_float4(x, y, z, n);
}

// ============================================================================
// 0b) spatial binning (order inside a cell nondeterministic; FPS tie-breaks on
//     ORIGINAL index so the result is placement-invariant).
// ============================================================================
__global__ void binit_kernel() {
    int t = threadIdx.x;
    for (int k = t; k < NCELLS; k += 256) { g_hist[k] = 0; g_coff[k] = 0; }
    if (t < 3) g_benc[t] = 0xFFFFFFFFu;
    if (t >= 3 && t < 6) g_benc[t] = 0u;
}

__global__ void bbox_kernel(const float* __restrict__ pos) {
    int i = blockIdx.x * blockDim.x + threadIdx.x;
    unsigned ex = fenc(pos[3 * i + 0]);
    unsigned ey = fenc(pos[3 * i + 1]);
    unsigned ez = fenc(pos[3 * i + 2]);
    unsigned mnx = ~__reduce_max_sync(0xFFFFFFFFu, ~ex);
    unsigned mny = ~__reduce_max_sync(0xFFFFFFFFu, ~ey);
    unsigned mnz = ~__reduce_max_sync(0xFFFFFFFFu, ~ez);
    unsigned mxx = __reduce_max_sync(0xFFFFFFFFu, ex);
    unsigned mxy = __reduce_max_sync(0xFFFFFFFFu, ey);
    unsigned mxz = __reduce_max_sync(0xFFFFFFFFu, ez);
    if ((threadIdx.x & 31) == 0) {
        atomicMin(&g_benc[0], mnx); atomicMin(&g_benc[1], mny); atomicMin(&g_benc[2], mnz);
        atomicMax(&g_benc[3], mxx); atomicMax(&g_benc[4], mxy); atomicMax(&g_benc[5], mxz);
    }
}

__global__ void cell_kernel(const float* __restrict__ pos) {
    int i = blockIdx.x * blockDim.x + threadIdx.x;
    float mnx = fdec(g_benc[0]), mny = fdec(g_benc[1]), mnz = fdec(g_benc[2]);
    float mxx = fdec(g_benc[3]), mxy = fdec(g_benc[4]), mxz = fdec(g_benc[5]);
    float sx = 16.0f / fmaxf(mxx - mnx, 1e-20f);
    float sy = 16.0f / fmaxf(mxy - mny, 1e-20f);
    float sz = 16.0f / fmaxf(mxz - mnz, 1e-20f);
    int ix = min(15, max(0, (int)((pos[3 * i + 0] - mnx) * sx)));
    int iy = min(15, max(0, (int)((pos[3 * i + 1] - mny) * sy)));
    int iz = min(15, max(0, (int)((pos[3 * i + 2] - mnz) * sz)));
    int cell = (int)(spread3((unsigned)ix) | (spread3((unsigned)iy) << 1) |
                     (spread3((unsigned)iz) << 2));
    g_cell[i] = cell;
    atomicAdd(&g_hist[cell], 1);
}

__global__ void prefix_kernel() {
    __shared__ int part[256];
    __shared__ int base[256];
    int t = threadIdx.x;
    int loc[16];
    int s = 0;
#pragma unroll
    for (int k = 0; k < 16; ++k) { loc[k] = s; s += g_hist[t * 16 + k]; }
    part[t] = s;
    __syncthreads();
    if (t == 0) {
        int acc = 0;
        for (int i = 0; i < 256; ++i) { base[i] = acc; acc += part[i]; }
    }
    __syncthreads();
#pragma unroll
    for (int k = 0; k < 16; ++k) g_hist[t * 16 + k] = base[t] + loc[k];
}

__global__ void scatter_kernel(const float* __restrict__ pos) {
    int i = blockIdx.x * blockDim.x + threadIdx.x;
    int cell = g_cell[i];
    int p = g_hist[cell] + atomicAdd(&g_coff[cell], 1);
    g_spos[p] = make_float4(pos[3 * i + 0], pos[3 * i + 1], pos[3 * i + 2],
                            __int_as_float(i));
}

// ============================================================================
// 1) FPS: 8-CTA cluster, bucket-pruned, single-warp mbarrier rendezvous.
//    Exact f32, reference op order ((dx2+dy2)+dz2). Skip rule (exact): if
//    dmin2(center,bbox)*(1-1e-5) > max(md) the fminf update is a no-op.
//    Argmax key = (md_bits<<32)|(~orig_idx) -> first-original-index ties.
//
//    Sync per round:
//      warps 1..15: write slot -> bar.arrive 1 -> bar.sync 2 -> read center
//      warp 0:      bar.sync 1 -> REDUX 16 slots -> lanes 0-7 push {key,xy,z}
//                   + mbarrier.arrive.release to peer `lane` -> wait LOCAL
//                   mbarrier (count 8) -> cross reduce -> center to smem ->
//                   bar.sync 2.
//    Two alternating mbarriers (by it&1) + parity waits + parity-buffered
//    slots: an early arrive for round it+2 lands on the OTHER barrier, and
//    the wait(it+1) <- arrive(it+1) <- wait(it) chain bounds skew to 1 round,
//    so counts can never mix and buffer overwrites happen-after all reads.
// ============================================================================
__global__ void __cluster_dims__(FPS_CTAS, 1, 1) __launch_bounds__(FPS_THREADS, 1)
fps_kernel(const float* __restrict__ pos) {
    __shared__ unsigned long long s_wslots[2][16][3];   // [key, xy, z]
    __shared__ unsigned long long s_cross[2][FPS_CTAS][3];
    __shared__ __align__(8) unsigned long long s_mbar[2];
    __shared__ unsigned long long s_ctr[2][2];          // [par][xy, z]

    const int tid = threadIdx.x;
    const int lane = tid & 31;
    const int wid = tid >> 5;
    const unsigned rank = cluster_rank();
    const int p0 = (int)(rank * FPS_THREADS + tid) * PPT;

    const unsigned cross_base = (unsigned)__cvta_generic_to_shared(&s_cross[0][0][0]);
    const unsigned mbar_base = (unsigned)__cvta_generic_to_shared(&s_mbar[0]);

    if (tid == 0) {
        asm volatile("mbarrier.init.shared.b64 [%0], %1;"
                     :: "r"(mbar_base), "r"(FPS_CTAS) : "memory");
        asm volatile("mbarrier.init.shared.b64 [%0], %1;"
                     :: "r"(mbar_base + 8), "r"(FPS_CTAS) : "memory");
        if (rank == 0) g_idx[0] = 0;
    }

    unsigned long long X[PPT / 2], Y[PPT / 2], Z[PPT / 2];
    float md[PPT];
    int oi[PPT];
    float bxlo = finf(), bylo = finf(), bzlo = finf();
    float bxhi = fninf(), byhi = fninf(), bzhi = fninf();
#pragma unroll
    for (int j = 0; j < PPT; ++j) {
        float4 p = g_spos[p0 + j];
        oi[j] = __float_as_int(p.w);
        md[j] = finf();
        bxlo = fminf(bxlo, p.x); bxhi = fmaxf(bxhi, p.x);
        bylo = fminf(bylo, p.y); byhi = fmaxf(byhi, p.y);
        bzlo = fminf(bzlo, p.z); bzhi = fmaxf(bzhi, p.z);
        if (j & 1) {
            float4 q = g_spos[p0 + j - 1];
            X[j >> 1] = pk2(q.x, p.x);
            Y[j >> 1] = pk2(q.y, p.y);
            Z[j >> 1] = pk2(q.z, p.z);
        }
    }

    unsigned long long Bkey = ((unsigned long long)0x7f800000u << 32);  // md=inf
    int jwin = 0;

    float cx = pos[0], cy = pos[1], cz = pos[2];

    // mbarriers initialized in all CTAs before any cross-CTA arrive
    asm volatile("barrier.cluster.arrive.aligned;" ::: "memory");
    asm volatile("barrier.cluster.wait.aligned;" ::: "memory");

    unsigned ph[2] = {0u, 0u};

    for (int it = 1; it < MCL; ++it) {
        const int par = it & 1;

        // ---- exact bucket-prune test ----
        float Bval = __uint_as_float((unsigned)(Bkey >> 32));
        float ddx = fmaxf(fmaxf(bxlo - cx, cx - bxhi), 0.0f);
        float ddy = fmaxf(fmaxf(bylo - cy, cy - byhi), 0.0f);
        float ddz = fmaxf(fmaxf(bzlo - cz, cz - bzhi), 0.0f);
        float dmin2 = ddx * ddx + ddy * ddy + ddz * ddz;
        bool active = !(dmin2 * 0.99999f > Bval);

        if (active) {
            unsigned long long ncx = pk2(-cx, -cx);
            unsigned long long ncy = pk2(-cy, -cy);
            unsigned long long ncz = pk2(-cz, -cz);
#pragma unroll
            for (int pr = 0; pr < PPT / 2; ++pr) {
                unsigned long long ax = add2(X[pr], ncx);   // p + (-c) == p - c (exact)
                unsigned long long ay = add2(Y[pr], ncy);
                unsigned long long az = add2(Z[pr], ncz);
                unsigned long long sx = mul2(ax, ax);
                unsigned long long sy = mul2(ay, ay);
                unsigned long long sz = mul2(az, az);
                unsigned long long s = add2(add2(sx, sy), sz);  // (dx2+dy2)+dz2
                float d0, d1;
                upk2(s, d0, d1);
                md[2 * pr + 0] = fminf(md[2 * pr + 0], d0);
                md[2 * pr + 1] = fminf(md[2 * pr + 1], d1);
            }
            unsigned long long bk = 0ULL;
            int jw = 0;
#pragma unroll
            for (int j = 0; j < PPT; ++j) {
                unsigned long long k =
                    ((unsigned long long)__float_as_uint(md[j]) << 32) |
                    (unsigned)(0xFFFFFFFFu - (unsigned)oi[j]);
                if (k > bk) { bk = k; jw = j; }
            }
            Bkey = bk;
            jwin = jw;
        }

        // ---- warp argmax via REDUX ----
        unsigned bvb = (unsigned)(Bkey >> 32);
        unsigned mylo = (unsigned)Bkey;
        unsigned wmax = __reduce_max_sync(0xFFFFFFFFu, bvb);
        unsigned lowc = (bvb == wmax) ? mylo : 0u;
        unsigned wlow = __reduce_max_sync(0xFFFFFFFFu, lowc);
        unsigned ball = __ballot_sync(0xFFFFFFFFu, (bvb == wmax) && (mylo == wlow));
        int owner = __ffs(ball) - 1;

        // ---- branchless coord extraction; predicated slot store ----
        int j = jwin;
        unsigned long long vx = (j & 4) ? ((j & 2) ? X[3] : X[2])
                                        : ((j & 2) ? X[1] : X[0]);
        unsigned long long vy = (j & 4) ? ((j & 2) ? Y[3] : Y[2])
                                        : ((j & 2) ? Y[1] : Y[0]);
        unsigned long long vz = (j & 4) ? ((j & 2) ? Z[3] : Z[2])
                                        : ((j & 2) ? Z[1] : Z[0]);
        float x0, x1, y0, y1, z0, z1;
        upk2(vx, x0, x1); upk2(vy, y0, y1); upk2(vz, z0, z1);
        float px = (j & 1) ? x1 : x0;
        float py = (j & 1) ? y1 : y0;
        float pz = (j & 1) ? z1 : z0;
        if (lane == owner) {
            s_wslots[par][wid][0] = ((unsigned long long)wmax << 32) | wlow;
            s_wslots[par][wid][1] = pk2(px, py);
            s_wslots[par][wid][2] = pk2(pz, 0.0f);
        }

        if (wid != 0) {
            // producers: signal slot, then block until center is published
            asm volatile("bar.arrive 1, %0;" :: "r"(FPS_THREADS) : "memory");
            asm volatile("bar.sync 2, %0;" :: "r"(FPS_THREADS) : "memory");
            float dummy;
            upk2(s_ctr[par][0], cx, cy);
            upk2(s_ctr[par][1], cz, dummy);
        } else {
            asm volatile("bar.sync 1, %0;" :: "r"(FPS_THREADS) : "memory");

            unsigned hi = 0u, lo = 0u;
            if (lane < 16) {
                unsigned long long k = s_wslots[par][lane][0];
                hi = (unsigned)(k >> 32);
                lo = (unsigned)k;
            }
            unsigned mhi = __reduce_max_sync(0xFFFFFFFFu, hi);
            unsigned lom = (hi == mhi) ? lo : 0u;
            unsigned mlo = __reduce_max_sync(0xFFFFFFFFu, lom);
            unsigned b2 = __ballot_sync(0xFFFFFFFFu,
                                        (hi == mhi) && (lo == mlo) && (lane < 16));
            int w = __ffs(b2) - 1;
            unsigned long long kk = ((unsigned long long)mhi << 32) | mlo;
            unsigned long long xy = s_wslots[par][w][1];
            unsigned long long zz = s_wslots[par][w][2];
            if (lane < FPS_CTAS) {
                unsigned base = cross_base +
                                (unsigned)((par * FPS_CTAS + (int)rank) * 3) * 8u;
                st_cluster_u64(base + 0, (unsigned)lane, kk);
                st_cluster_u64(base + 8, (unsigned)lane, xy);
                st_cluster_u64(base + 16, (unsigned)lane, zz);
                mbar_arrive_remote(mbar_base + (unsigned)par * 8u, (unsigned)lane);
            }

            mbar_wait_cluster(mbar_base + (unsigned)par * 8u, ph[par]);
            ph[par] ^= 1;

            // all 32 lanes redundantly reduce the 8 cross keys
            unsigned long long g = s_cross[par][0][0];
            int rw = 0;
#pragma unroll
            for (int r = 1; r < FPS_CTAS; ++r) {
                unsigned long long k2 = s_cross[par][r][0];
                if (k2 > g) { g = k2; rw = r; }
            }
            float dummy;
            upk2(s_cross[par][rw][1], cx, cy);
            upk2(s_cross[par][rw][2], cz, dummy);
            if (lane == 0) {
                s_ctr[par][0] = s_cross[par][rw][1];
                s_ctr[par][1] = s_cross[par][rw][2];
                if (rank == 0)
                    g_idx[it] = (int)(0xFFFFFFFFu - (unsigned)g);
            }
            asm volatile("bar.sync 2, %0;" :: "r"(FPS_THREADS) : "memory");
        }
    }
}

// ============================================================================
// 2) meta: sub_pos / sub_batch outputs
// ============================================================================
__global__ void meta_kernel(const float* __restrict__ pos,
                            const int* __restrict__ batch,
                            float* outPos, int* outBatch,
                            int writePos, int writeBatch) {
    int m = blockIdx.x * blockDim.x + threadIdx.x;
    if (m >= MCL) return;
    int idx = g_idx[m];
    if (writePos) {
        outPos[3 * m + 0] = pos[3 * idx + 0];
        outPos[3 * m + 1] = pos[3 * idx + 1];
        outPos[3 * m + 2] = pos[3 * idx + 2];
    }
    if (writeBatch) outBatch[m] = batch[idx];
}

// ============================================================================
// 3) kNN: 8 lanes/query (measured best), smem-tiled pos4, register top-16,
//    shuffle pop-merge. d = (|q|^2 - 2*dot) + |p|^2, exact f32.
// ============================================================================
#define KNN_TILE 2048
__global__ void __launch_bounds__(256) knn_kernel() {
    __shared__ float4 s_p[KNN_TILE];
    const int tid = threadIdx.x;
    const int q = blockIdx.x * 32 + (tid >> 3);
    const int s = tid & 7;

    const int ci = g_idx[q];
    const float4 qp = g_pos4[ci];

    float dist[KNN_K];
    int idn[KNN_K];
#pragma unroll
    for (int u = 0; u < KNN_K; ++u) { dist[u] = finf(); idn[u] = 0; }

    for (int t0 = 0; t0 < NPTS; t0 += KNN_TILE) {
        __syncthreads();
        for (int i = tid; i < KNN_TILE; i += 256) s_p[i] = g_pos4[t0 + i];
        __syncthreads();
        for (int t = s; t < KNN_TILE; t += 8) {
            float4 p = s_p[t];
            float dot = __fadd_rn(__fadd_rn(__fmul_rn(qp.x, p.x),
                                            __fmul_rn(qp.y, p.y)),
                                  __fmul_rn(qp.z, p.z));
            float d = __fadd_rn(__fsub_rn(qp.w, __fmul_rn(2.0f, dot)), p.w);
            if (d < dist[KNN_K - 1]) {
                dist[KNN_K - 1] = d;
                idn[KNN_K - 1] = t0 + t;
#pragma unroll
                for (int u = KNN_K - 1; u > 0; --u) {
                    if (dist[u] < dist[u - 1]) {
                        float td = dist[u]; dist[u] = dist[u - 1]; dist[u - 1] = td;
                        int ti = idn[u]; idn[u] = idn[u - 1]; idn[u - 1] = ti;
                    }
                }
            }
        }
    }

#pragma unroll 1
    for (int r = 0; r < KNN_K; ++r) {
        unsigned db = __float_as_uint(dist[0]);
        db = (db & 0x80000000u) ? ~db : (db | 0x80000000u);  // total order
        unsigned long long key =
            ((unsigned long long)db << 32) |
            (unsigned)((idn[0] << 3) | s);
#pragma unroll
        for (int o = 1; o < 8; o <<= 1) {
            unsigned long long k2 = __shfl_xor_sync(0xFFFFFFFFu, key, o, 8);
            if (k2 < key) key = k2;
        }
        int wl = (int)(key & 7u);
        int hid = (int)((key >> 3) & 0x7FFFu);
        if (s == 0) g_nbr[q * KNN_K + r] = hid;
        if (s == wl) {  // pop my head
#pragma unroll
            for (int u = 0; u < KNN_K - 1; ++u) {
                dist[u] = dist[u + 1];
                idn[u] = idn[u + 1];
            }
            dist[KNN_K - 1] = finf();
        }
    }
}

// ============================================================================
// 4) GEMM: h = x @ W + b, exact f32 FFMA, 64x64 tiles
// ============================================================================
__global__ void __launch_bounds__(256) gemm_kernel(const float* __restrict__ Xm,
                                                   const float* __restrict__ Wm,
                                                   const float* __restrict__ Bv) {
    __shared__ __align__(16) float As[32][72];
    __shared__ __align__(16) float Bs[32][64];

    const int tid = threadIdx.x;
    const int tx = tid & 15, ty = tid >> 4;
    const int r0 = blockIdx.x * 64;
    const int c0 = blockIdx.y * 64;

    float acc[4][4];
#pragma unroll
    for (int i = 0; i < 4; ++i)
#pragma unroll
        for (int j = 0; j < 4; ++j) acc[i][j] = 0.0f;

    for (int kc = 0; kc < CIN; kc += 32) {
        __syncthreads();
#pragma unroll
        for (int l = 0; l < 2; ++l) {
            int fi = tid * 2 + l;
            int row = fi >> 3;
            int kf = fi & 7;
            float4 a = *(const float4*)&Xm[(r0 + row) * CIN + kc + kf * 4];
            As[kf * 4 + 0][row] = a.x;
            As[kf * 4 + 1][row] = a.y;
            As[kf * 4 + 2][row] = a.z;
            As[kf * 4 + 3][row] = a.w;
        }
#pragma unroll
        for (int l = 0; l < 2; ++l) {
            int fi = tid * 2 + l;
            int kk = fi >> 4;
            int cf = fi & 15;
            *(float4*)&Bs[kk][cf * 4] =
                *(const float4*)&Wm[(kc + kk) * COUT + c0 + cf * 4];
        }
        __syncthreads();
#pragma unroll
        for (int kk = 0; kk < 32; ++kk) {
            float4 a = *(float4*)&As[kk][ty * 4];
            float4 b = *(float4*)&Bs[kk][tx * 4];
            float av[4] = {a.x, a.y, a.z, a.w};
            float bv[4] = {b.x, b.y, b.z, b.w};
#pragma unroll
            for (int i = 0; i < 4; ++i)
#pragma unroll
                for (int j = 0; j < 4; ++j) acc[i][j] = fmaf(av[i], bv[j], acc[i][j]);
        }
    }

    float4 bias = *(const float4*)&Bv[c0 + tx * 4];
#pragma unroll
    for (int i = 0; i < 4; ++i) {
        float4 o;
        o.x = acc[i][0] + bias.x;
        o.y = acc[i][1] + bias.y;
        o.z = acc[i][2] + bias.z;
        o.w = acc[i][3] + bias.w;
        *(float4*)&g_h[(r0 + ty * 4 + i) * COUT + c0 + tx * 4] = o;
    }
}

// ============================================================================
// 5) BatchNorm stats: deterministic two-stage tree (no float atomics)
// ============================================================================
__global__ void bn_part_kernel() {
    const int c = threadIdx.x;
    const int b = blockIdx.x;
    const float* hp = g_h + (size_t)b * 128 * COUT;
    float s = 0.0f, ss = 0.0f;
#pragma unroll 4
    for (int r = 0; r < 128; ++r) {
        float v = hp[r * COUT + c];
        s += v;
        ss = fmaf(v, v, ss);
    }
    g_psum[b * COUT + c] = s;
    g_psumsq[b * COUT + c] = ss;
}

__global__ void bn_final_kernel(const float* __restrict__ gamma,
                                const float* __restrict__ beta) {
    const int c = threadIdx.x;
    float s = 0.0f, ss = 0.0f;
    for (int b = 0; b < 256; ++b) {
        s += g_psum[b * COUT + c];
        ss += g_psumsq[b * COUT + c];
    }
    const float invN = 1.0f / (float)NPTS;
    float mu = s * invN;
    float var = ss * invN - mu * mu;
    var = fmaxf(var, 0.0f);
    float sc = gamma[c] * (1.0f / sqrtf(var + 1e-5f));
    g_scale[c] = sc;
    g_shift[c] = beta[c] - mu * sc;
}

// ============================================================================
// 6) gather-max with fused BN+ReLU per gathered element
// ============================================================================
__global__ void __launch_bounds__(256) gather_kernel(float* __restrict__ out) {
    const int m = blockIdx.x;
    const int c = threadIdx.x;
    const float sc = g_scale[c];
    const float sh = g_shift[c];
    float acc = fninf();
#pragma unroll
    for (int k = 0; k < KNN_K; ++k) {
        int id = g_nbr[m * KNN_K + k];
        float v = g_h[(size_t)id * COUT + c];
        float bn = fmaxf(fmaf(v, sc, sh), 0.0f);
        acc = fmaxf(acc, bn);
    }
    out[m * COUT + c] = acc;
}

// ============================================================================
// launch
// ============================================================================
extern "C" void kernel_launch(void* const* d_in, const int* in_sizes, int n_in,
                              void* d_out, int out_size) {
    const float* x     = (const float*)d_in[0];  // [32768,128]
    const float* pos   = (const float*)d_in[1];  // [32768,3]
    const int*   batch = (const int*)d_in[2];    // [32768]
    const float* W     = (const float*)d_in[3];  // [128,256]
    const float* b     = (const float*)d_in[4];  // [256]
    const float* gamma = (const float*)d_in[5];  // [256]
    const float* beta  = (const float*)d_in[6];  // [256]
    float* out = (float*)d_out;

    const int baseOut = MCL * COUT;              // 2097152
    const int writePos = (out_size >= baseOut + MCL * 3) ? 1 : 0;
    const int writeBatch = (out_size >= baseOut + MCL * 3 + MCL) ? 1 : 0;

    prep_kernel<<<NPTS / 256, 256>>>(pos);
    binit_kernel<<<1, 256>>>();
    bbox_kernel<<<NPTS / 256, 256>>>(pos);
    cell_kernel<<<NPTS / 256, 256>>>(pos);
    prefix_kernel<<<1, 256>>>();
    scatter_kernel<<<NPTS / 256, 256>>>(pos);
    fps_kernel<<<FPS_CTAS, FPS_THREADS>>>(pos);
    meta_kernel<<<MCL / 256, 256>>>(pos, batch,
                                    out + baseOut,
                                    (int*)(out + baseOut + MCL * 3),
                                    writePos, writeBatch);
    knn_kernel<<<MCL / 32, 256>>>();
    gemm_kernel<<<dim3(NPTS / 64, COUT / 64), 256>>>(x, W, b);
    bn_part_kernel<<<256, 256>>>();
    bn_final_kernel<<<1, 256>>>(gamma, beta);
    gather_kernel<<<MCL, 256>>>(out);
}

// round 17
// speedup vs baseline: 1.4348x; 1.1346x over previous
#include <cuda_runtime.h>
#include <cuda_bf16.h>

// ============================================================================
// TransitionDown: FPS (M=8192 of N=32768) + kNN(16) + Linear+BN+ReLU + max-pool
// Output layout (float32): [out 8192x256][sub_pos 8192x3][sub_batch 8192]
// All arithmetic exact f32. FPS: single-CTA (1024 thr), warp-spread spatial
// buckets, exact bbox pruning, 2 named barriers per round. No cluster.
// ============================================================================

#define NPTS   32768
#define CIN    128
#define COUT   256
#define KNN_K  16
#define MCL    8192

#define NCELLS 4096     // 16^3 Morton grid

// ---------------- device scratch (static; no allocation allowed) ------------
__device__ float4  g_pos4[NPTS];           // {x,y,z, |p|^2} exact f32 (orig order)
__device__ float4  g_spos[NPTS];           // sorted {x,y,z, orig_idx bits}
__device__ float   g_smd[NPTS];            // per sorted point: current min dist
__device__ int     g_cell[NPTS];           // cell id per point
__device__ int     g_hist[NCELLS];         // counts -> exclusive bases
__device__ int     g_coff[NCELLS];         // scatter cursors
__device__ unsigned g_benc[6];             // encoded bbox: min x,y,z ; max x,y,z
__device__ int     g_idx[MCL];             // FPS-selected indices (original ids)
__device__ int     g_nbr[MCL * KNN_K];     // kNN indices
__device__ float   g_h[NPTS * COUT];       // linear output (pre-BN)
__device__ float   g_psum[256 * COUT];
__device__ float   g_psumsq[256 * COUT];
__device__ float   g_scale[COUT];
__device__ float   g_shift[COUT];

// ---------------- small helpers ---------------------------------------------
__device__ __forceinline__ float finf() { return __int_as_float(0x7f800000); }
__device__ __forceinline__ float fninf() { return __int_as_float(0xff800000); }

__device__ __forceinline__ unsigned fenc(float f) {   // monotone float->u32
    unsigned b = __float_as_uint(f);
    return (b & 0x80000000u) ? ~b : (b | 0x80000000u);
}
__device__ __forceinline__ float fdec(unsigned e) {
    unsigned b = (e & 0x80000000u) ? (e & 0x7FFFFFFFu) : ~e;
    return __uint_as_float(b);
}

__device__ __forceinline__ unsigned long long pk2(float a, float b) {
    unsigned long long r;
    asm("mov.b64 %0, {%1, %2};" : "=l"(r) : "f"(a), "f"(b));
    return r;
}
__device__ __forceinline__ void upk2(unsigned long long v, float& a, float& b) {
    asm("mov.b64 {%0, %1}, %2;" : "=f"(a), "=f"(b) : "l"(v));
}
__device__ __forceinline__ unsigned spread3(unsigned x) {   // 4-bit -> every 3rd bit
    return (x & 1u) | ((x & 2u) << 2) | ((x & 4u) << 4) | ((x & 8u) << 6);
}

// ============================================================================
// 0) prep: pos4 table {x,y,z, |p|^2} exact f32
// ============================================================================
__global__ void prep_kernel(const float* __restrict__ pos) {
    int i = blockIdx.x * blockDim.x + threadIdx.x;
    if (i >= NPTS) return;
    float x = pos[3 * i + 0];
    float y = pos[3 * i + 1];
    float z = pos[3 * i + 2];
    float n = __fadd_rn(__fadd_rn(__fmul_rn(x, x), __fmul_rn(y, y)), __fmul_rn(z, z));
    g_pos4[i] = make_float4(x, y, z, n);
}

// ============================================================================
// 0b) spatial binning (order inside a cell nondeterministic; FPS tie-breaks on
//     ORIGINAL index so the result is placement-invariant).
// ============================================================================
__global__ void binit_kernel() {
    int t = threadIdx.x;
    for (int k = t; k < NCELLS; k += 256) { g_hist[k] = 0; g_coff[k] = 0; }
    if (t < 3) g_benc[t] = 0xFFFFFFFFu;
    if (t >= 3 && t < 6) g_benc[t] = 0u;
}

__global__ void bbox_kernel(const float* __restrict__ pos) {
    int i = blockIdx.x * blockDim.x + threadIdx.x;
    unsigned ex = fenc(pos[3 * i + 0]);
    unsigned ey = fenc(pos[3 * i + 1]);
    unsigned ez = fenc(pos[3 * i + 2]);
    unsigned mnx = __reduce_min_sync(0xFFFFFFFFu, ex);
    unsigned mny = __reduce_min_sync(0xFFFFFFFFu, ey);
    unsigned mnz = __reduce_min_sync(0xFFFFFFFFu, ez);
    unsigned mxx = __reduce_max_sync(0xFFFFFFFFu, ex);
    unsigned mxy = __reduce_max_sync(0xFFFFFFFFu, ey);
    unsigned mxz = __reduce_max_sync(0xFFFFFFFFu, ez);
    if ((threadIdx.x & 31) == 0) {
        atomicMin(&g_benc[0], mnx); atomicMin(&g_benc[1], mny); atomicMin(&g_benc[2], mnz);
        atomicMax(&g_benc[3], mxx); atomicMax(&g_benc[4], mxy); atomicMax(&g_benc[5], mxz);
    }
}

__global__ void cell_kernel(const float* __restrict__ pos) {
    int i = blockIdx.x * blockDim.x + threadIdx.x;
    float mnx = fdec(g_benc[0]), mny = fdec(g_benc[1]), mnz = fdec(g_benc[2]);
    float mxx = fdec(g_benc[3]), mxy = fdec(g_benc[4]), mxz = fdec(g_benc[5]);
    float sx = 16.0f / fmaxf(mxx - mnx, 1e-20f);
    float sy = 16.0f / fmaxf(mxy - mny, 1e-20f);
    float sz = 16.0f / fmaxf(mxz - mnz, 1e-20f);
    int ix = min(15, max(0, (int)((pos[3 * i + 0] - mnx) * sx)));
    int iy = min(15, max(0, (int)((pos[3 * i + 1] - mny) * sy)));
    int iz = min(15, max(0, (int)((pos[3 * i + 2] - mnz) * sz)));
    int cell = (int)(spread3((unsigned)ix) | (spread3((unsigned)iy) << 1) |
                     (spread3((unsigned)iz) << 2));
    g_cell[i] = cell;
    atomicAdd(&g_hist[cell], 1);
}

__global__ void prefix_kernel() {
    __shared__ int part[256];
    __shared__ int base[256];
    int t = threadIdx.x;
    int loc[16];
    int s = 0;
#pragma unroll
    for (int k = 0; k < 16; ++k) { loc[k] = s; s += g_hist[t * 16 + k]; }
    part[t] = s;
    __syncthreads();
    if (t == 0) {
        int acc = 0;
        for (int i = 0; i < 256; ++i) { base[i] = acc; acc += part[i]; }
    }
    __syncthreads();
#pragma unroll
    for (int k = 0; k < 16; ++k) g_hist[t * 16 + k] = base[t] + loc[k];
}

__global__ void scatter_kernel(const float* __restrict__ pos) {
    int i = blockIdx.x * blockDim.x + threadIdx.x;
    int cell = g_cell[i];
    int p = g_hist[cell] + atomicAdd(&g_coff[cell], 1);
    g_spos[p] = make_float4(pos[3 * i + 0], pos[3 * i + 1], pos[3 * i + 2],
                            __int_as_float(i));
}

// ============================================================================
// 1) FPS: single CTA, 1024 threads (32 warps), 1024 buckets x 32 points.
//    Bucket b (32 consecutive Morton-sorted points) is owned by warp (b&31),
//    cached in lane (b>>5): adjacent buckets spread across warps so the few
//    buckets activated per round are processed in parallel, each 32-wide.
//
//    Exact f32, reference op order ((dx2+dy2)+dz2). Skip rule (exact): if
//    dmin2(center,bbox)*(1-1e-5) > Bval (bucket max md), every recomputed d
//    exceeds its md (fp margin ~6e-7), so the fminf update is a no-op.
//    Argmax key = (md_bits<<32)|(~orig_idx) -> first-original-index ties,
//    matching jnp.argmax over the original order.
//
//    Per point: touched by exactly one (warp,lane) forever -> g_smd accesses
//    are same-thread ordered, no fences needed.
//
//    Round sync: every warp's winner lane writes s_slot[wid]; producers
//    bar.arrive(1)+bar.sync(2); warp0 bar.sync(1), REDUX over 32 slots,
//    publishes center+g_idx, bar.sync(2). Single-buffered slots/center are
//    safe: warp0's reads precede its bar2 arrival, so any warp's round-(it+1)
//    slot write (after passing bar2) happens-after those reads; each producer
//    reads s_ctr before its next bar.arrive(1), and warp0 overwrites s_ctr
//    only after bar.sync(1) of the next round.
// ============================================================================
__global__ void __launch_bounds__(1024, 1) fps_kernel(const float* __restrict__ pos) {
    __shared__ unsigned long long s_slot[32][3];   // [key, xy, z]
    __shared__ unsigned long long s_ctr[2];        // xy, z

    const int tid = threadIdx.x;
    const int lane = tid & 31;
    const int wid = tid >> 5;
    const unsigned FULL = 0xFFFFFFFFu;

    // ---- per-bucket cached state (bucket b = lane*32 + wid) ----
    float bxlo = 0.f, bxhi = 0.f, bylo = 0.f, byhi = 0.f, bzlo = 0.f, bzhi = 0.f;
    unsigned Bhi = 0u, Blo = 0u;            // cached (md_max_bits, ~oi) key
    float Px = 0.f, Py = 0.f, Pz = 0.f;     // cached winner coords

    // init: cooperatively build each of this warp's 32 buckets
    for (int c = 0; c < 32; ++c) {
        int pi = (c * 32 + wid) * 32 + lane;
        float4 p = g_spos[pi];
        g_smd[pi] = finf();
        unsigned oib = __float_as_uint(p.w);
        unsigned exl = __reduce_min_sync(FULL, fenc(p.x));
        unsigned exh = __reduce_max_sync(FULL, fenc(p.x));
        unsigned eyl = __reduce_min_sync(FULL, fenc(p.y));
        unsigned eyh = __reduce_max_sync(FULL, fenc(p.y));
        unsigned ezl = __reduce_min_sync(FULL, fenc(p.z));
        unsigned ezh = __reduce_max_sync(FULL, fenc(p.z));
        unsigned lo = __reduce_max_sync(FULL, ~oib);   // md all inf -> min oi wins
        unsigned bl = __ballot_sync(FULL, (~oib) == lo);
        int src = __ffs(bl) - 1;
        float qx = __shfl_sync(FULL, p.x, src);
        float qy = __shfl_sync(FULL, p.y, src);
        float qz = __shfl_sync(FULL, p.z, src);
        if (lane == c) {
            bxlo = fdec(exl); bxhi = fdec(exh);
            bylo = fdec(eyl); byhi = fdec(eyh);
            bzlo = fdec(ezl); bzhi = fdec(ezh);
            Bhi = 0x7f800000u; Blo = lo;
            Px = qx; Py = qy; Pz = qz;
        }
    }

    float cx = pos[0], cy = pos[1], cz = pos[2];
    if (tid == 0) g_idx[0] = 0;

    for (int it = 1; it < MCL; ++it) {
        // ---- exact bucket prune test (my cached bucket) ----
        float Bval = __uint_as_float(Bhi);
        float ddx = fmaxf(fmaxf(bxlo - cx, cx - bxhi), 0.0f);
        float ddy = fmaxf(fmaxf(bylo - cy, cy - byhi), 0.0f);
        float ddz = fmaxf(fmaxf(bzlo - cz, cz - bzhi), 0.0f);
        float dmin2 = ddx * ddx + ddy * ddy + ddz * ddz;
        bool act = !(dmin2 * 0.99999f > Bval);
        unsigned mask = __ballot_sync(FULL, act);

        // ---- process active buckets 32-wide ----
        while (mask) {
            int c = __ffs(mask) - 1;
            mask &= mask - 1;
            int pi = (c * 32 + wid) * 32 + lane;
            float4 p = g_spos[pi];
            float m = g_smd[pi];
            float dx = __fsub_rn(p.x, cx);
            float dy = __fsub_rn(p.y, cy);
            float dz = __fsub_rn(p.z, cz);
            float d = __fadd_rn(__fadd_rn(__fmul_rn(dx, dx), __fmul_rn(dy, dy)),
                                __fmul_rn(dz, dz));          // (dx2+dy2)+dz2
            float nm = fminf(m, d);
            g_smd[pi] = nm;
            unsigned hi = __float_as_uint(nm);
            unsigned whi = __reduce_max_sync(FULL, hi);       // md >= 0: bit==val order
            unsigned oib = __float_as_uint(p.w);
            unsigned cand = (hi == whi) ? ~oib : 0u;
            unsigned wlo = __reduce_max_sync(FULL, cand);     // max ~oi == min oi
            unsigned bl = __ballot_sync(FULL, (hi == whi) && (cand == wlo));
            int src = __ffs(bl) - 1;
            float qx = __shfl_sync(FULL, p.x, src);
            float qy = __shfl_sync(FULL, p.y, src);
            float qz = __shfl_sync(FULL, p.z, src);
            if (lane == c) { Bhi = whi; Blo = wlo; Px = qx; Py = qy; Pz = qz; }
        }

        // ---- warp winner over 32 cached bucket keys; winner lane writes slot ----
        {
            unsigned whi = __reduce_max_sync(FULL, Bhi);
            unsigned cand = (Bhi == whi) ? Blo : 0u;
            unsigned wlo = __reduce_max_sync(FULL, cand);
            unsigned bl = __ballot_sync(FULL, (Bhi == whi) && (Blo == wlo));
            int src = __ffs(bl) - 1;
            if (lane == src) {
                s_slot[wid][0] = ((unsigned long long)whi << 32) | wlo;
                s_slot[wid][1] = pk2(Px, Py);
                s_slot[wid][2] = pk2(Pz, 0.0f);
            }
        }

        if (wid != 0) {
            asm volatile("bar.arrive 1, 1024;" ::: "memory");
            asm volatile("bar.sync 2, 1024;" ::: "memory");
        } else {
            asm volatile("bar.sync 1, 1024;" ::: "memory");
            unsigned long long k = s_slot[lane][0];
            unsigned hi2 = (unsigned)(k >> 32), lo2 = (unsigned)k;
            unsigned mhi = __reduce_max_sync(FULL, hi2);
            unsigned c2 = (hi2 == mhi) ? lo2 : 0u;
            unsigned mlo = __reduce_max_sync(FULL, c2);
            unsigned b2 = __ballot_sync(FULL, (hi2 == mhi) && (lo2 == mlo));
            int w = __ffs(b2) - 1;
            if (lane == 0) {
                s_ctr[0] = s_slot[w][1];
                s_ctr[1] = s_slot[w][2];
                g_idx[it] = (int)(~mlo);
            }
            asm volatile("bar.sync 2, 1024;" ::: "memory");
        }
        float dummy;
        upk2(s_ctr[0], cx, cy);
        upk2(s_ctr[1], cz, dummy);
    }
}

// ============================================================================
// 2) meta: sub_pos / sub_batch outputs
// ============================================================================
__global__ void meta_kernel(const float* __restrict__ pos,
                            const int* __restrict__ batch,
                            float* outPos, int* outBatch,
                            int writePos, int writeBatch) {
    int m = blockIdx.x * blockDim.x + threadIdx.x;
    if (m >= MCL) return;
    int idx = g_idx[m];
    if (writePos) {
        outPos[3 * m + 0] = pos[3 * idx + 0];
        outPos[3 * m + 1] = pos[3 * idx + 1];
        outPos[3 * m + 2] = pos[3 * idx + 2];
    }
    if (writeBatch) outBatch[m] = batch[idx];
}

// ============================================================================
// 3) kNN: 8 lanes/query (measured best), smem-tiled pos4, register top-16,
//    shuffle pop-merge. d = (|q|^2 - 2*dot) + |p|^2, exact f32.
// ============================================================================
#define KNN_TILE 2048
__global__ void __launch_bounds__(256) knn_kernel() {
    __shared__ float4 s_p[KNN_TILE];
    const int tid = threadIdx.x;
    const int q = blockIdx.x * 32 + (tid >> 3);
    const int s = tid & 7;

    const int ci = g_idx[q];
    const float4 qp = g_pos4[ci];

    float dist[KNN_K];
    int idn[KNN_K];
#pragma unroll
    for (int u = 0; u < KNN_K; ++u) { dist[u] = finf(); idn[u] = 0; }

    for (int t0 = 0; t0 < NPTS; t0 += KNN_TILE) {
        __syncthreads();
        for (int i = tid; i < KNN_TILE; i += 256) s_p[i] = g_pos4[t0 + i];
        __syncthreads();
        for (int t = s; t < KNN_TILE; t += 8) {
            float4 p = s_p[t];
            float dot = __fadd_rn(__fadd_rn(__fmul_rn(qp.x, p.x),
                                            __fmul_rn(qp.y, p.y)),
                                  __fmul_rn(qp.z, p.z));
            float d = __fadd_rn(__fsub_rn(qp.w, __fmul_rn(2.0f, dot)), p.w);
            if (d < dist[KNN_K - 1]) {
                dist[KNN_K - 1] = d;
                idn[KNN_K - 1] = t0 + t;
#pragma unroll
                for (int u = KNN_K - 1; u > 0; --u) {
                    if (dist[u] < dist[u - 1]) {
                        float td = dist[u]; dist[u] = dist[u - 1]; dist[u - 1] = td;
                        int ti = idn[u]; idn[u] = idn[u - 1]; idn[u - 1] = ti;
                    }
                }
            }
        }
    }

#pragma unroll 1
    for (int r = 0; r < KNN_K; ++r) {
        unsigned db = __float_as_uint(dist[0]);
        db = (db & 0x80000000u) ? ~db : (db | 0x80000000u);  // total order
        unsigned long long key =
            ((unsigned long long)db << 32) |
            (unsigned)((idn[0] << 3) | s);
#pragma unroll
        for (int o = 1; o < 8; o <<= 1) {
            unsigned long long k2 = __shfl_xor_sync(0xFFFFFFFFu, key, o, 8);
            if (k2 < key) key = k2;
        }
        int wl = (int)(key & 7u);
        int hid = (int)((key >> 3) & 0x7FFFu);
        if (s == 0) g_nbr[q * KNN_K + r] = hid;
        if (s == wl) {  // pop my head
#pragma unroll
            for (int u = 0; u < KNN_K - 1; ++u) {
                dist[u] = dist[u + 1];
                idn[u] = idn[u + 1];
            }
            dist[KNN_K - 1] = finf();
        }
    }
}

// ============================================================================
// 4) GEMM: h = x @ W + b, exact f32 FFMA, 64x64 tiles
// ============================================================================
__global__ void __launch_bounds__(256) gemm_kernel(const float* __restrict__ Xm,
                                                   const float* __restrict__ Wm,
                                                   const float* __restrict__ Bv) {
    __shared__ __align__(16) float As[32][72];
    __shared__ __align__(16) float Bs[32][64];

    const int tid = threadIdx.x;
    const int tx = tid & 15, ty = tid >> 4;
    const int r0 = blockIdx.x * 64;
    const int c0 = blockIdx.y * 64;

    float acc[4][4];
#pragma unroll
    for (int i = 0; i < 4; ++i)
#pragma unroll
        for (int j = 0; j < 4; ++j) acc[i][j] = 0.0f;

    for (int kc = 0; kc < CIN; kc += 32) {
        __syncthreads();
#pragma unroll
        for (int l = 0; l < 2; ++l) {
            int fi = tid * 2 + l;
            int row = fi >> 3;
            int kf = fi & 7;
            float4 a = *(const float4*)&Xm[(r0 + row) * CIN + kc + kf * 4];
            As[kf * 4 + 0][row] = a.x;
            As[kf * 4 + 1][row] = a.y;
            As[kf * 4 + 2][row] = a.z;
            As[kf * 4 + 3][row] = a.w;
        }
#pragma unroll
        for (int l = 0; l < 2; ++l) {
            int fi = tid * 2 + l;
            int kk = fi >> 4;
            int cf = fi & 15;
            *(float4*)&Bs[kk][cf * 4] =
                *(const float4*)&Wm[(kc + kk) * COUT + c0 + cf * 4];
        }
        __syncthreads();
#pragma unroll
        for (int kk = 0; kk < 32; ++kk) {
            float4 a = *(float4*)&As[kk][ty * 4];
            float4 b = *(float4*)&Bs[kk][tx * 4];
            float av[4] = {a.x, a.y, a.z, a.w};
            float bv[4] = {b.x, b.y, b.z, b.w};
#pragma unroll
            for (int i = 0; i < 4; ++i)
#pragma unroll
                for (int j = 0; j < 4; ++j) acc[i][j] = fmaf(av[i], bv[j], acc[i][j]);
        }
    }

    float4 bias = *(const float4*)&Bv[c0 + tx * 4];
#pragma unroll
    for (int i = 0; i < 4; ++i) {
        float4 o;
        o.x = acc[i][0] + bias.x;
        o.y = acc[i][1] + bias.y;
        o.z = acc[i][2] + bias.z;
        o.w = acc[i][3] + bias.w;
        *(float4*)&g_h[(r0 + ty * 4 + i) * COUT + c0 + tx * 4] = o;
    }
}

// ============================================================================
// 5) BatchNorm stats: deterministic two-stage tree (no float atomics)
// ============================================================================
__global__ void bn_part_kernel() {
    const int c = threadIdx.x;
    const int b = blockIdx.x;
    const float* hp = g_h + (size_t)b * 128 * COUT;
    float s = 0.0f, ss = 0.0f;
#pragma unroll 4
    for (int r = 0; r < 128; ++r) {
        float v = hp[r * COUT + c];
        s += v;
        ss = fmaf(v, v, ss);
    }
    g_psum[b * COUT + c] = s;
    g_psumsq[b * COUT + c] = ss;
}

__global__ void bn_final_kernel(const float* __restrict__ gamma,
                                const float* __restrict__ beta) {
    const int c = threadIdx.x;
    float s = 0.0f, ss = 0.0f;
    for (int b = 0; b < 256; ++b) {
        s += g_psum[b * COUT + c];
        ss += g_psumsq[b * COUT + c];
    }
    const float invN = 1.0f / (float)NPTS;
    float mu = s * invN;
    float var = ss * invN - mu * mu;
    var = fmaxf(var, 0.0f);
    float sc = gamma[c] * (1.0f / sqrtf(var + 1e-5f));
    g_scale[c] = sc;
    g_shift[c] = beta[c] - mu * sc;
}

// ============================================================================
// 6) gather-max with fused BN+ReLU per gathered element
// ============================================================================
__global__ void __launch_bounds__(256) gather_kernel(float* __restrict__ out) {
    const int m = blockIdx.x;
    const int c = threadIdx.x;
    const float sc = g_scale[c];
    const float sh = g_shift[c];
    float acc = fninf();
#pragma unroll
    for (int k = 0; k < KNN_K; ++k) {
        int id = g_nbr[m * KNN_K + k];
        float v = g_h[(size_t)id * COUT + c];
        float bn = fmaxf(fmaf(v, sc, sh), 0.0f);
        acc = fmaxf(acc, bn);
    }
    out[m * COUT + c] = acc;
}

// ============================================================================
// launch
// ============================================================================
extern "C" void kernel_launch(void* const* d_in, const int* in_sizes, int n_in,
                              void* d_out, int out_size) {
    const float* x     = (const float*)d_in[0];  // [32768,128]
    const float* pos   = (const float*)d_in[1];  // [32768,3]
    const int*   batch = (const int*)d_in[2];    // [32768]
    const float* W     = (const float*)d_in[3];  // [128,256]
    const float* b     = (const float*)d_in[4];  // [256]
    const float* gamma = (const float*)d_in[5];  // [256]
    const float* beta  = (const float*)d_in[6];  // [256]
    float* out = (float*)d_out;

    const int baseOut = MCL * COUT;              // 2097152
    const int writePos = (out_size >= baseOut + MCL * 3) ? 1 : 0;
    const int writeBatch = (out_size >= baseOut + MCL * 3 + MCL) ? 1 : 0;

    prep_kernel<<<NPTS / 256, 256>>>(pos);
    binit_kernel<<<1, 256>>>();
    bbox_kernel<<<NPTS / 256, 256>>>(pos);
    cell_kernel<<<NPTS / 256, 256>>>(pos);
    prefix_kernel<<<1, 256>>>();
    scatter_kernel<<<NPTS / 256, 256>>>(pos);
    fps_kernel<<<1, 1024>>>(pos);
    meta_kernel<<<MCL / 256, 256>>>(pos, batch,
                                    out + baseOut,
                                    (int*)(out + baseOut + MCL * 3),
                                    writePos, writeBatch);
    knn_kernel<<<MCL / 32, 256>>>();
    gemm_kernel<<<dim3(NPTS / 64, COUT / 64), 256>>>(x, W, b);
    bn_part_kernel<<<256, 256>>>();
    bn_final_kernel<<<1, 256>>>(gamma, beta);
    gather_kernel<<<MCL, 256>>>(out);
}